// round 14
// baseline (speedup 1.0000x reference)
#include <cuda_runtime.h>
#include <cuda_fp16.h>
#include <stdint.h>

// ============================================================================
// GPT block, sm_100-safe mma.sync.
//   QKV      : fused 3-pass fp16 GEMM (Q,K pair out; V fp32 out)
//   scores   : fused dual-acc int8 (q8h*k8l & q8l*k8h) + fp16 Qh*Kh RMW
//   attn@V / FFN1 / FFN2 : int8 DOUBLE-LEVEL single-kernel GEMMs
// R14: i8d tiles 128x64, acc 64 regs -> 2 CTAs/SM.
// ============================================================================

typedef __half h16;

// ---------------- helpers ----------------
__device__ __forceinline__ uint32_t smem_u32(const void* p) {
    uint32_t a;
    asm("{ .reg .u64 t; cvta.to.shared.u64 t, %1; cvt.u32.u64 %0, t; }"
        : "=r"(a) : "l"(p));
    return a;
}
__device__ __forceinline__ void cp16(uint32_t saddr, const void* g) {
    asm volatile("cp.async.cg.shared.global [%0], [%1], 16;"
                 :: "r"(saddr), "l"(g) : "memory");
}
#define CP_COMMIT() asm volatile("cp.async.commit_group;" ::: "memory")
#define CP_WAIT1()  asm volatile("cp.async.wait_group 1;" ::: "memory")

__device__ __forceinline__ void ldsm4(uint32_t* r, uint32_t a) {
    asm volatile("ldmatrix.sync.aligned.m8n8.x4.shared.b16 {%0,%1,%2,%3}, [%4];"
                 : "=r"(r[0]), "=r"(r[1]), "=r"(r[2]), "=r"(r[3]) : "r"(a));
}
__device__ __forceinline__ void mma16816(float* c, const uint32_t* a,
                                         const uint32_t* b) {
    asm volatile(
        "mma.sync.aligned.m16n8k16.row.col.f32.f16.f16.f32 "
        "{%0,%1,%2,%3}, {%4,%5,%6,%7}, {%8,%9}, {%0,%1,%2,%3};"
        : "+f"(c[0]), "+f"(c[1]), "+f"(c[2]), "+f"(c[3])
        : "r"(a[0]), "r"(a[1]), "r"(a[2]), "r"(a[3]), "r"(b[0]), "r"(b[1]));
}
__device__ __forceinline__ void mma_s8(int* c, const uint32_t* a,
                                       const uint32_t* b) {
    asm volatile(
        "mma.sync.aligned.m16n8k32.row.col.s32.s8.s8.s32 "
        "{%0,%1,%2,%3}, {%4,%5,%6,%7}, {%8,%9}, {%0,%1,%2,%3};"
        : "+r"(c[0]), "+r"(c[1]), "+r"(c[2]), "+r"(c[3])
        : "r"(a[0]), "r"(a[1]), "r"(a[2]), "r"(a[3]), "r"(b[0]), "r"(b[1]));
}

__device__ __forceinline__ uint32_t swz(int r, int s) {
    return (uint32_t)(r * 64 + ((s ^ ((r >> 1) & 3)) << 4));
}
__device__ __forceinline__ void split2h(float v, h16& h, h16& l) {
    h = __float2half(v);
    l = __float2half(v - __half2float(h));
}
__device__ __forceinline__ int clamp127(int x) {
    return x < -127 ? -127 : (x > 127 ? 127 : x);
}

// ---------------- scratch ----------------
__device__ h16 g_Xh[16384LL * 768], g_Xl[16384LL * 768];
__device__ h16 g_Wch[2304LL * 768], g_Wcl[2304LL * 768];
__device__ h16 g_Qh[4LL * 4096 * 768], g_Ql[4LL * 4096 * 768];
__device__ h16 g_Kh[4LL * 4096 * 768], g_Kl[4LL * 4096 * 768];
__device__ float g_Vf[4LL * 4096 * 768];
__device__ float g_VTf[4LL * 768 * 4096];
__device__ float g_S[4LL * 4096 * 4096];
__device__ h16 g_NVh[4LL * 4096 * 768], g_NVl[4LL * 4096 * 768];
__device__ h16 g_Hh[16384LL * 3072], g_Hl[16384LL * 3072];
__device__ char g_q8h[16384LL * 768], g_q8l[16384LL * 768];
__device__ char g_k8h[16384LL * 768], g_k8l[16384LL * 768];
__device__ float g_sqh[16384], g_sql[16384], g_skh[16384], g_skl[16384];
__device__ char g_p8a[16384LL * 4096], g_p8b[16384LL * 4096];
__device__ char g_vt8a[3072LL * 4096], g_vt8b[3072LL * 4096];
__device__ char g_nv8a[16384LL * 768], g_nv8b[16384LL * 768];
__device__ char g_h8a[16384LL * 3072], g_h8b[16384LL * 3072];
__device__ char g_w18a[3072 * 768], g_w18b[3072 * 768];
__device__ char g_w28a[768 * 3072], g_w28b[768 * 3072];
__device__ float g_sp[16384], g_svt[3072], g_snv[16384], g_sH[16384];
__device__ float g_sw1[3072], g_sw2[768];

// ---------------- fp16 GEMM (QKV route + scores hi-pass) ----------------
static constexpr int STAGE_BYTES = 32768;
static constexpr int SMEM_TOTAL  = 3 * STAGE_BYTES;

template <int PASSES>
__device__ __forceinline__ void load_stage(
    uint32_t so, int tid,
    const h16* __restrict__ Ah, const h16* __restrict__ Al,
    const h16* __restrict__ Bh, const h16* __restrict__ Bl,
    long long k0, int K)
{
    const int r = tid & 127, h = tid >> 7;
#pragma unroll
    for (int u = 0; u < 2; ++u) {
        const uint32_t d = swz(r, h * 2 + u);
        const long long g = (long long)r * K + k0 + (h * 2 + u) * 8;
        cp16(so + d,         Ah + g);
        if (PASSES >= 2) cp16(so + 8192 + d, Al + g);
        cp16(so + 16384 + d, Bh + g);
        if (PASSES == 3)  cp16(so + 24576 + d, Bl + g);
    }
}

// OM: 2 = f32 accumulate in-place, 3 = fused QKV routing
template <int PASSES, int OM>
__global__ __launch_bounds__(256, 2)
void wm_gemm(const h16* __restrict__ Ahi, const h16* __restrict__ Alo,
             const h16* __restrict__ Bhi, const h16* __restrict__ Blo,
             float* __restrict__ Cf, h16* __restrict__ Chi, h16* __restrict__ Clo,
             h16* __restrict__ C2hi, h16* __restrict__ C2lo,
             const int N, const int K,
             const long long bA, const long long bB, const long long bC)
{
    extern __shared__ __align__(128) char smem[];
    const uint32_t sb = smem_u32(smem);
    const int tid = threadIdx.x;
    const int wid = tid >> 5, lane = tid & 31;
    const int wm = wid >> 1, wn = wid & 1;
    const int lj = lane >> 3, lr = lane & 7;

    const long long bm = (long long)blockIdx.y * 128;
    const long long bn = (long long)blockIdx.x * 128;

    const h16* Ah = Ahi + (long long)blockIdx.z * bA + bm * K;
    const h16* Al = (PASSES >= 2) ? (Alo + (long long)blockIdx.z * bA + bm * K) : nullptr;
    const h16* Bh = Bhi + (long long)blockIdx.z * bB + bn * K;
    const h16* Bl = (PASSES == 3) ? (Blo + (long long)blockIdx.z * bB + bn * K) : nullptr;

    float acc[2][8][4];
#pragma unroll
    for (int i = 0; i < 2; ++i)
#pragma unroll
        for (int j = 0; j < 8; ++j)
#pragma unroll
            for (int t = 0; t < 4; ++t) acc[i][j][t] = 0.0f;

    const int NC = K / 32;
    load_stage<PASSES>(sb, tid, Ah, Al, Bh, Bl, 0, K);
    CP_COMMIT();
    load_stage<PASSES>(sb + STAGE_BYTES, tid, Ah, Al, Bh, Bl, 32, K);
    CP_COMMIT();

    const int arow = wm * 32 + ((lj & 1) << 3) + lr;
    const int aseg = lj >> 1;
    const int brow = wn * 64 + ((lj >> 1) << 3) + lr;
    const int bseg = lj & 1;

    int buf = 0;
    for (int c = 0; c < NC; ++c) {
        CP_WAIT1();
        __syncthreads();
        if (c + 2 < NC) {
            int nb = buf + 2; if (nb >= 3) nb -= 3;
            load_stage<PASSES>(sb + nb * STAGE_BYTES, tid, Ah, Al, Bh, Bl,
                               (long long)(c + 2) * 32, K);
        }
        CP_COMMIT();

        const uint32_t bb = sb + buf * STAGE_BYTES;
#pragma unroll
        for (int ks = 0; ks < 2; ++ks) {
            uint32_t Afh[2][4], Afl[2][4];
#pragma unroll
            for (int mt = 0; mt < 2; ++mt) {
                const uint32_t off = swz(arow + mt * 16, ks * 2 + aseg);
                ldsm4(Afh[mt], bb + off);
                if (PASSES >= 2) ldsm4(Afl[mt], bb + 8192 + off);
            }
#pragma unroll
            for (int ntp = 0; ntp < 4; ++ntp) {
                const uint32_t off = swz(brow + ntp * 16, ks * 2 + bseg);
                uint32_t Bfh[4];
                ldsm4(Bfh, bb + 16384 + off);
                uint32_t Bfl[4];
                if (PASSES == 3) ldsm4(Bfl, bb + 24576 + off);
#pragma unroll
                for (int mt = 0; mt < 2; ++mt)
#pragma unroll
                    for (int h = 0; h < 2; ++h) {
                        float* cc = acc[mt][ntp * 2 + h];
                        mma16816(cc, Afh[mt], &Bfh[h * 2]);
                        if (PASSES >= 2) mma16816(cc, Afl[mt], &Bfh[h * 2]);
                        if (PASSES == 3) mma16816(cc, Afh[mt], &Bfl[h * 2]);
                    }
            }
        }
        ++buf; if (buf == 3) buf = 0;
    }

    const long long zC = (long long)blockIdx.z * bC;
    const int rbase = (int)bm + wm * 32 + (lane >> 2);
    const int seg   = (OM == 3) ? (int)(bn / 768) : 0;
    const int cbase = (OM == 3)
        ? ((int)bn - seg * 768 + wn * 64 + (lane & 3) * 2)
        : ((int)bn + wn * 64 + (lane & 3) * 2);
    const int cstride = (OM == 3) ? 768 : N;

#pragma unroll
    for (int mt = 0; mt < 2; ++mt)
#pragma unroll
        for (int nt = 0; nt < 8; ++nt) {
            const int col = cbase + nt * 8;
#pragma unroll
            for (int rh = 0; rh < 2; ++rh) {
                const int row = rbase + mt * 16 + rh * 8;
                float v0 = acc[mt][nt][rh * 2 + 0];
                float v1 = acc[mt][nt][rh * 2 + 1];
                const long long o = zC + (long long)row * cstride + col;
                if (OM == 2) {
                    float2 t = *(const float2*)(Cf + o);
                    t.x += v0; t.y += v1;
                    *(float2*)(Cf + o) = t;
                } else {  // OM == 3: QKV routing
                    if (seg == 0) {
                        h16 h0, l0, h1, l1;
                        split2h(v0, h0, l0); split2h(v1, h1, l1);
                        *(__half2*)(Chi + o) = __halves2half2(h0, h1);
                        *(__half2*)(Clo + o) = __halves2half2(l0, l1);
                    } else if (seg == 1) {
                        h16 h0, l0, h1, l1;
                        split2h(v0, h0, l0); split2h(v1, h1, l1);
                        *(__half2*)(C2hi + o) = __halves2half2(h0, h1);
                        *(__half2*)(C2lo + o) = __halves2half2(l0, l1);
                    } else {
                        float2 w; w.x = v0; w.y = v1;
                        *(float2*)(Cf + o) = w;
                    }
                }
            }
        }
}

// ---------------- dual-accumulator int8 GEMM, 128x64 tiles ----------------
// MODE 0: scores-corr: val = sa1*sb1*acc1 + sa2*sb2*acc2       -> f32 INIT
// MODE 1: double-lvl : val = sa1*sb1*(acc1 + acc2/256)         -> pair out
// MODE 2: double-lvl + bias + relu                             -> pair out
// MODE 3: double-lvl + bias                                    -> f32 out
// stage: A1@0 (8KB), A2@8192, B1@16384 (4KB), B2@20480; stride 24KB x3 = 72KB
static constexpr int I8D_STAGE = 24576;
static constexpr int I8D_SMEM  = 3 * I8D_STAGE;

__device__ __forceinline__ void i8d_load(uint32_t so, int tid,
    const char* __restrict__ A1, const char* __restrict__ A2,
    const char* __restrict__ B1, const char* __restrict__ B2,
    long long k0, int K)
{
    const int r = tid & 127, hf = tid >> 7;
#pragma unroll
    for (int u = 0; u < 2; ++u) {
        const int s = hf * 2 + u;
        const uint32_t d = swz(r, s);
        const long long g = (long long)r * K + k0 + s * 16;
        cp16(so + d,        A1 + g);
        cp16(so + 8192 + d, A2 + g);
    }
    {
        const int rb = tid & 63, sb2 = tid >> 6;           // 64 rows x 4 segs
        const uint32_t d = swz(rb, sb2);
        const long long g = (long long)rb * K + k0 + sb2 * 16;
        cp16(so + 16384 + d, B1 + g);
        cp16(so + 20480 + d, B2 + g);
    }
}

template <int MODE>
__global__ __launch_bounds__(256, 2)
void i8d_gemm(const char* __restrict__ A1, const char* __restrict__ A2,
              const char* __restrict__ B1, const char* __restrict__ B2,
              const float* __restrict__ sa1, const float* __restrict__ sa2,
              const float* __restrict__ sb1, const float* __restrict__ sb2,
              const float* __restrict__ bias,
              float* __restrict__ Cf, h16* __restrict__ Chi, h16* __restrict__ Clo,
              const int N, const int K,
              const long long bA, const long long bB, const long long bC,
              const int sAz, const int sBz)
{
    extern __shared__ __align__(128) char smem[];
    const uint32_t sbase = smem_u32(smem);
    const int tid = threadIdx.x;
    const int wid = tid >> 5, lane = tid & 31;
    const int wm = wid >> 1, wn = wid & 1;          // 4m x 2n, warp tile 32x32
    const int lj = lane >> 3, lr = lane & 7;
    const int z = blockIdx.z;
    const long long bm = (long long)blockIdx.y * 128;
    const long long bn = (long long)blockIdx.x * 64;

    const char* A1b = A1 + (long long)z * bA + bm * K;
    const char* A2b = A2 + (long long)z * bA + bm * K;
    const char* B1b = B1 + (long long)z * bB + bn * K;
    const char* B2b = B2 + (long long)z * bB + bn * K;
    const float* sa1v = sa1 + (long long)z * sAz + bm;
    const float* sb1v = sb1 + (long long)z * sBz + bn;
    const float* sa2v = (MODE == 0) ? (sa2 + (long long)z * sAz + bm) : nullptr;
    const float* sb2v = (MODE == 0) ? (sb2 + (long long)z * sBz + bn) : nullptr;

    int acc1[2][4][4], acc2[2][4][4];
#pragma unroll
    for (int i = 0; i < 2; ++i)
#pragma unroll
        for (int j = 0; j < 4; ++j)
#pragma unroll
            for (int t = 0; t < 4; ++t) { acc1[i][j][t] = 0; acc2[i][j][t] = 0; }

    const int NC = K / 64;
    i8d_load(sbase, tid, A1b, A2b, B1b, B2b, 0, K);
    CP_COMMIT();
    i8d_load(sbase + I8D_STAGE, tid, A1b, A2b, B1b, B2b, 64, K);
    CP_COMMIT();

    // s8 fragment order == fp16 order (R9): row-block fastest for A
    const int arow = wm * 32 + ((lj & 1) << 3) + lr;
    const int aso  = lj >> 1;
    const int brow = wn * 32 + ((lj >> 1) << 3) + lr;
    const int bso  = lj & 1;

    int buf = 0;
    for (int c = 0; c < NC; ++c) {
        CP_WAIT1();
        __syncthreads();
        if (c + 2 < NC) {
            int nb = buf + 2; if (nb >= 3) nb -= 3;
            i8d_load(sbase + nb * I8D_STAGE, tid, A1b, A2b, B1b, B2b,
                     (long long)(c + 2) * 64, K);
        }
        CP_COMMIT();

        const uint32_t bb = sbase + buf * I8D_STAGE;
#pragma unroll
        for (int step = 0; step < 2; ++step) {
            uint32_t A1f[2][4], A2f[2][4];
#pragma unroll
            for (int mt = 0; mt < 2; ++mt) {
                const uint32_t off = swz(arow + mt * 16, step * 2 + aso);
                ldsm4(A1f[mt], bb + off);
                ldsm4(A2f[mt], bb + 8192 + off);
            }
#pragma unroll
            for (int ntp = 0; ntp < 2; ++ntp) {
                const uint32_t off = swz(brow + ntp * 16, step * 2 + bso);
                uint32_t B1f[4], B2f[4];
                ldsm4(B1f, bb + 16384 + off);
                ldsm4(B2f, bb + 20480 + off);
#pragma unroll
                for (int mt = 0; mt < 2; ++mt)
#pragma unroll
                    for (int h = 0; h < 2; ++h) {
                        int* c1 = acc1[mt][ntp * 2 + h];
                        int* c2 = acc2[mt][ntp * 2 + h];
                        mma_s8(c1, A1f[mt], &B1f[h * 2]);
                        if (MODE == 0) {
                            mma_s8(c2, A2f[mt], &B2f[h * 2]);
                        } else {
                            mma_s8(c2, A1f[mt], &B2f[h * 2]);
                            mma_s8(c2, A2f[mt], &B1f[h * 2]);
                        }
                    }
            }
        }
        ++buf; if (buf == 3) buf = 0;
    }

    // epilogue
    const int rb = wm * 32 + (lane >> 2);
    const int cb = wn * 32 + (lane & 3) * 2;
    const long long zC = (long long)z * bC;
#pragma unroll
    for (int mt = 0; mt < 2; ++mt)
#pragma unroll
        for (int rh = 0; rh < 2; ++rh) {
            const int lrw = rb + mt * 16 + rh * 8;
            const float sA1 = sa1v[lrw];
            const float sA2 = (MODE == 0) ? sa2v[lrw] : 0.f;
#pragma unroll
            for (int nt = 0; nt < 4; ++nt) {
                const int lc = cb + nt * 8;
                const int x1a = acc1[mt][nt][rh * 2 + 0];
                const int x1b = acc1[mt][nt][rh * 2 + 1];
                const int x2a = acc2[mt][nt][rh * 2 + 0];
                const int x2b = acc2[mt][nt][rh * 2 + 1];
                float v0, v1;
                if (MODE == 0) {
                    v0 = sA1 * sb1v[lc]     * (float)x1a + sA2 * sb2v[lc]     * (float)x2a;
                    v1 = sA1 * sb1v[lc + 1] * (float)x1b + sA2 * sb2v[lc + 1] * (float)x2b;
                } else {
                    v0 = sA1 * sb1v[lc]     * ((float)x1a + (float)x2a * 0.00390625f);
                    v1 = sA1 * sb1v[lc + 1] * ((float)x1b + (float)x2b * 0.00390625f);
                }
                if (MODE >= 2) {
                    v0 += bias[(int)bn + lc];
                    v1 += bias[(int)bn + lc + 1];
                }
                if (MODE == 2) { v0 = fmaxf(v0, 0.f); v1 = fmaxf(v1, 0.f); }
                const long long o = zC + (bm + lrw) * N + bn + lc;
                if (MODE == 0 || MODE == 3) {
                    float2 w; w.x = v0; w.y = v1;
                    *(float2*)(Cf + o) = w;
                } else {
                    h16 h0, l0, h1, l1;
                    split2h(v0, h0, l0); split2h(v1, h1, l1);
                    *(__half2*)(Chi + o) = __halves2half2(h0, h1);
                    *(__half2*)(Clo + o) = __halves2half2(l0, l1);
                }
            }
        }
}

// ---------------- per-row int8 quant of fp16 pair, L=768 (scores Q/K) --------
__global__ __launch_bounds__(256)
void quant_rows(const h16* __restrict__ Ah, const h16* __restrict__ Al,
                char* __restrict__ q8h, char* __restrict__ q8l,
                float* __restrict__ sh, float* __restrict__ sl)
{
    __shared__ float red[8][2];
    const long long row = blockIdx.x;
    const int tid = threadIdx.x, lane = tid & 31, warp = tid >> 5;
    const h16* ph = Ah + row * 768;
    const h16* pl = Al + row * 768;

    float vh[3], vl[3];
    float mh = 0.f, ml = 0.f;
#pragma unroll
    for (int i = 0; i < 3; ++i) {
        vh[i] = __half2float(ph[tid + i * 256]);
        vl[i] = __half2float(pl[tid + i * 256]);
        mh = fmaxf(mh, fabsf(vh[i]));
        ml = fmaxf(ml, fabsf(vl[i]));
    }
#pragma unroll
    for (int o = 16; o > 0; o >>= 1) {
        mh = fmaxf(mh, __shfl_xor_sync(0xffffffffu, mh, o));
        ml = fmaxf(ml, __shfl_xor_sync(0xffffffffu, ml, o));
    }
    if (lane == 0) { red[warp][0] = mh; red[warp][1] = ml; }
    __syncthreads();
    mh = red[0][0]; ml = red[0][1];
#pragma unroll
    for (int w = 1; w < 8; ++w) {
        mh = fmaxf(mh, red[w][0]);
        ml = fmaxf(ml, red[w][1]);
    }
    mh = fmaxf(mh, 1e-20f);
    ml = fmaxf(ml, 1e-20f);
    const float ih = 127.f / mh, il = 127.f / ml;
#pragma unroll
    for (int i = 0; i < 3; ++i) {
        q8h[row * 768 + tid + i * 256] = (char)__float2int_rn(vh[i] * ih);
        q8l[row * 768 + tid + i * 256] = (char)__float2int_rn(vl[i] * il);
    }
    if (tid == 0) { sh[row] = mh / 127.f; sl[row] = ml / 127.f; }
}

// ---------------- per-row double-level quant of fp16 pair ----------------
__global__ __launch_bounds__(256)
void quant_pd(const h16* __restrict__ Ah, const h16* __restrict__ Al,
              char* __restrict__ q1, char* __restrict__ q2,
              float* __restrict__ s, const int L)
{
    __shared__ float red[8];
    const long long row = blockIdx.x;
    const int tid = threadIdx.x, lane = tid & 31, warp = tid >> 5;
    const h16* ph = Ah + row * (long long)L;
    const h16* pl = Al + row * (long long)L;

    float m = 0.f;
    for (int i = tid; i < L; i += 256)
        m = fmaxf(m, fabsf(__half2float(ph[i]) + __half2float(pl[i])));
#pragma unroll
    for (int o = 16; o > 0; o >>= 1)
        m = fmaxf(m, __shfl_xor_sync(0xffffffffu, m, o));
    if (lane == 0) red[warp] = m;
    __syncthreads();
    m = red[0];
#pragma unroll
    for (int w = 1; w < 8; ++w) m = fmaxf(m, red[w]);
    m = fmaxf(m, 1e-20f);
    const float inv = 127.f / m;
    char* p1 = q1 + row * (long long)L;
    char* p2 = q2 + row * (long long)L;
    for (int i = tid; i < L; i += 256) {
        const float v = (__half2float(ph[i]) + __half2float(pl[i])) * inv;
        const int a = __float2int_rn(v);
        p1[i] = (char)a;
        p2[i] = (char)clamp127(__float2int_rn((v - (float)a) * 256.f));
    }
    if (tid == 0) s[row] = m / 127.f;
}

// ---------------- per-row double-level quant of fp32 rows ----------------
__global__ __launch_bounds__(256)
void quant_f32d(const float* __restrict__ A, char* __restrict__ q1,
                char* __restrict__ q2, float* __restrict__ s, const int L)
{
    __shared__ float red[8];
    const long long row = blockIdx.x;
    const int tid = threadIdx.x, lane = tid & 31, warp = tid >> 5;
    const float* p = A + row * (long long)L;

    float m = 0.f;
    for (int i = tid; i < L; i += 256)
        m = fmaxf(m, fabsf(p[i]));
#pragma unroll
    for (int o = 16; o > 0; o >>= 1)
        m = fmaxf(m, __shfl_xor_sync(0xffffffffu, m, o));
    if (lane == 0) red[warp] = m;
    __syncthreads();
    m = red[0];
#pragma unroll
    for (int w = 1; w < 8; ++w) m = fmaxf(m, red[w]);
    m = fmaxf(m, 1e-20f);
    const float inv = 127.f / m;
    char* p1 = q1 + row * (long long)L;
    char* p2 = q2 + row * (long long)L;
    for (int i = tid; i < L; i += 256) {
        const float v = p[i] * inv;
        const int a = __float2int_rn(v);
        p1[i] = (char)a;
        p2[i] = (char)clamp127(__float2int_rn((v - (float)a) * 256.f));
    }
    if (tid == 0) s[row] = m / 127.f;
}

// ---------------- fp32 -> (hi,lo) fp16 ----------------
__global__ __launch_bounds__(256)
void cvt_pair(const float* __restrict__ in, h16* __restrict__ hi,
              h16* __restrict__ lo, const long long n)
{
    const long long i = ((long long)blockIdx.x * 256 + threadIdx.x) * 4;
    if (i >= n) return;
    const float4 v = *(const float4*)(in + i);
    __align__(8) h16 h[4];
    __align__(8) h16 l[4];
    split2h(v.x, h[0], l[0]); split2h(v.y, h[1], l[1]);
    split2h(v.z, h[2], l[2]); split2h(v.w, h[3], l[3]);
    *(uint2*)(hi + i) = *(const uint2*)h;
    *(uint2*)(lo + i) = *(const uint2*)l;
}

// ---------------- V transpose: [b,4096,768]f32 -> [b,768,4096] fp32 ----------
__global__ __launch_bounds__(256)
void transpose_f32(const float* __restrict__ V, float* __restrict__ T)
{
    __shared__ float tile[32][33];
    const int b = blockIdx.z;
    const int e0 = blockIdx.x * 32;
    const int t0 = blockIdx.y * 32;
    const float* Vb = V + (long long)b * 4096 * 768;
    float* Tb = T + (long long)b * 768 * 4096;
    const int tx = threadIdx.x, ty = threadIdx.y;
#pragma unroll
    for (int j = 0; j < 32; j += 8)
        tile[ty + j][tx] = Vb[(long long)(t0 + ty + j) * 768 + e0 + tx];
    __syncthreads();
#pragma unroll
    for (int j = 0; j < 32; j += 8)
        Tb[(long long)(e0 + ty + j) * 4096 + t0 + tx] = tile[tx][ty + j];
}

// ---------------- softmax (rows of 4096) -> double-level int8 ----------------
__global__ __launch_bounds__(256)
void softmax_i8(const float* __restrict__ S, char* __restrict__ p8a,
                char* __restrict__ p8b, float* __restrict__ sp)
{
    __shared__ float red[8];
    const long long row = blockIdx.x;
    const float* p = S + row * 4096;
    const int tid = threadIdx.x, lane = tid & 31, warp = tid >> 5;

    float4 v[4];
#pragma unroll
    for (int i = 0; i < 4; ++i)
        v[i] = *(const float4*)(p + tid * 4 + i * 1024);

    float mx = -3.402823466e38f;
#pragma unroll
    for (int i = 0; i < 4; ++i)
        mx = fmaxf(mx, fmaxf(fmaxf(v[i].x, v[i].y), fmaxf(v[i].z, v[i].w)));
#pragma unroll
    for (int o = 16; o > 0; o >>= 1)
        mx = fmaxf(mx, __shfl_xor_sync(0xffffffffu, mx, o));
    if (lane == 0) red[warp] = mx;
    __syncthreads();
    float rowmax = red[0];
#pragma unroll
    for (int w = 1; w < 8; ++w) rowmax = fmaxf(rowmax, red[w]);
    __syncthreads();

    float sum = 0.0f;
#pragma unroll
    for (int i = 0; i < 4; ++i) {
        v[i].x = __expf(v[i].x - rowmax);
        v[i].y = __expf(v[i].y - rowmax);
        v[i].z = __expf(v[i].z - rowmax);
        v[i].w = __expf(v[i].w - rowmax);
        sum += (v[i].x + v[i].y) + (v[i].z + v[i].w);
    }
#pragma unroll
    for (int o = 16; o > 0; o >>= 1)
        sum += __shfl_xor_sync(0xffffffffu, sum, o);
    if (lane == 0) red[warp] = sum;
    __syncthreads();
    float rowsum = 0.0f;
#pragma unroll
    for (int w = 0; w < 8; ++w) rowsum += red[w];

#pragma unroll
    for (int i = 0; i < 4; ++i) {
        int q1[4], q2[4];
        const float e[4] = {v[i].x, v[i].y, v[i].z, v[i].w};
#pragma unroll
        for (int t = 0; t < 4; ++t) {
            const float u = 127.f * e[t];
            q1[t] = __float2int_rn(u);
            q2[t] = clamp127(__float2int_rn((u - (float)q1[t]) * 256.f));
        }
        const long long o = row * 4096 + tid * 4 + i * 1024;
        uint32_t w1 = ((uint32_t)(uint8_t)(char)q1[0])
                    | ((uint32_t)(uint8_t)(char)q1[1] << 8)
                    | ((uint32_t)(uint8_t)(char)q1[2] << 16)
                    | ((uint32_t)(uint8_t)(char)q1[3] << 24);
        uint32_t w2 = ((uint32_t)(uint8_t)(char)q2[0])
                    | ((uint32_t)(uint8_t)(char)q2[1] << 8)
                    | ((uint32_t)(uint8_t)(char)q2[2] << 16)
                    | ((uint32_t)(uint8_t)(char)q2[3] << 24);
        *(uint32_t*)(p8a + o) = w1;
        *(uint32_t*)(p8b + o) = w2;
    }
    if (tid == 0) sp[row] = (1.0f / rowsum) / 127.f;
}

// ---------------- host ----------------
extern "C" void kernel_launch(void* const* d_in, const int* in_sizes, int n_in,
                              void* d_out, int out_size)
{
    const float* X  = (const float*)d_in[0];
    const float* Wq = (const float*)d_in[1];
    const float* Wk = (const float*)d_in[2];
    const float* Wv = (const float*)d_in[3];
    const float* W1 = (const float*)d_in[4];
    const float* b1 = (const float*)d_in[5];
    const float* W2 = (const float*)d_in[6];
    const float* b2 = (const float*)d_in[7];
    float* out = (float*)d_out;

    h16 *Xh, *Xl, *Wch, *Wcl, *Qh, *Ql, *Kh, *Kl, *NVh, *NVl, *Hh, *Hl;
    float *Vf, *VTf, *S;
    char *q8h, *q8l, *k8h, *k8l;
    float *sqh, *sql, *skh, *skl;
    char *p8a, *p8b, *vt8a, *vt8b, *nv8a, *nv8b, *h8a, *h8b;
    char *w18a, *w18b, *w28a, *w28b;
    float *sp, *svt, *snv, *sH, *sw1, *sw2;
    cudaGetSymbolAddress((void**)&Xh, g_Xh);     cudaGetSymbolAddress((void**)&Xl, g_Xl);
    cudaGetSymbolAddress((void**)&Wch, g_Wch);   cudaGetSymbolAddress((void**)&Wcl, g_Wcl);
    cudaGetSymbolAddress((void**)&Qh, g_Qh);     cudaGetSymbolAddress((void**)&Ql, g_Ql);
    cudaGetSymbolAddress((void**)&Kh, g_Kh);     cudaGetSymbolAddress((void**)&Kl, g_Kl);
    cudaGetSymbolAddress((void**)&Vf, g_Vf);     cudaGetSymbolAddress((void**)&VTf, g_VTf);
    cudaGetSymbolAddress((void**)&S, g_S);
    cudaGetSymbolAddress((void**)&NVh, g_NVh);   cudaGetSymbolAddress((void**)&NVl, g_NVl);
    cudaGetSymbolAddress((void**)&Hh, g_Hh);     cudaGetSymbolAddress((void**)&Hl, g_Hl);
    cudaGetSymbolAddress((void**)&q8h, g_q8h);   cudaGetSymbolAddress((void**)&q8l, g_q8l);
    cudaGetSymbolAddress((void**)&k8h, g_k8h);   cudaGetSymbolAddress((void**)&k8l, g_k8l);
    cudaGetSymbolAddress((void**)&sqh, g_sqh);   cudaGetSymbolAddress((void**)&sql, g_sql);
    cudaGetSymbolAddress((void**)&skh, g_skh);   cudaGetSymbolAddress((void**)&skl, g_skl);
    cudaGetSymbolAddress((void**)&p8a, g_p8a);   cudaGetSymbolAddress((void**)&p8b, g_p8b);
    cudaGetSymbolAddress((void**)&vt8a, g_vt8a); cudaGetSymbolAddress((void**)&vt8b, g_vt8b);
    cudaGetSymbolAddress((void**)&nv8a, g_nv8a); cudaGetSymbolAddress((void**)&nv8b, g_nv8b);
    cudaGetSymbolAddress((void**)&h8a, g_h8a);   cudaGetSymbolAddress((void**)&h8b, g_h8b);
    cudaGetSymbolAddress((void**)&w18a, g_w18a); cudaGetSymbolAddress((void**)&w18b, g_w18b);
    cudaGetSymbolAddress((void**)&w28a, g_w28a); cudaGetSymbolAddress((void**)&w28b, g_w28b);
    cudaGetSymbolAddress((void**)&sp, g_sp);     cudaGetSymbolAddress((void**)&svt, g_svt);
    cudaGetSymbolAddress((void**)&snv, g_snv);   cudaGetSymbolAddress((void**)&sH, g_sH);
    cudaGetSymbolAddress((void**)&sw1, g_sw1);   cudaGetSymbolAddress((void**)&sw2, g_sw2);

    cudaFuncSetAttribute(wm_gemm<3, 3>,
                         cudaFuncAttributeMaxDynamicSharedMemorySize, SMEM_TOTAL);
    cudaFuncSetAttribute(wm_gemm<1, 2>,
                         cudaFuncAttributeMaxDynamicSharedMemorySize, SMEM_TOTAL);
    cudaFuncSetAttribute(i8d_gemm<0>,
                         cudaFuncAttributeMaxDynamicSharedMemorySize, I8D_SMEM);
    cudaFuncSetAttribute(i8d_gemm<1>,
                         cudaFuncAttributeMaxDynamicSharedMemorySize, I8D_SMEM);
    cudaFuncSetAttribute(i8d_gemm<2>,
                         cudaFuncAttributeMaxDynamicSharedMemorySize, I8D_SMEM);
    cudaFuncSetAttribute(i8d_gemm<3>,
                         cudaFuncAttributeMaxDynamicSharedMemorySize, I8D_SMEM);

    // 0-4 (launch #5 = QKV GEMM for the ncu window)
    cvt_pair<<<12288, 256>>>(X,  Xh,  Xl,  16384LL * 768);
    cvt_pair<<<576,  256>>>(Wq, Wch,              Wcl,              768LL * 768);
    cvt_pair<<<576,  256>>>(Wk, Wch + 768 * 768,  Wcl + 768 * 768,  768LL * 768);
    cvt_pair<<<576,  256>>>(Wv, Wch + 1536 * 768, Wcl + 1536 * 768, 768LL * 768);
    quant_f32d<<<3072, 256>>>(W1, w18a, w18b, sw1, 768);

    // fused QKV: Q,K pair out; V fp32 out
    wm_gemm<3, 3><<<dim3(18, 128, 1), 256, SMEM_TOTAL>>>(
        Xh, Xl, Wch, Wcl, Vf, Qh, Ql, Kh, Kl, 2304, 768, 0, 0, 0);

    quant_rows<<<16384, 256>>>(Qh, Ql, q8h, q8l, sqh, sql);
    quant_rows<<<16384, 256>>>(Kh, Kl, k8h, k8l, skh, skl);
    quant_f32d<<<768, 256>>>(W2, w28a, w28b, sw2, 3072);
    transpose_f32<<<dim3(24, 128, 4), dim3(32, 8)>>>(Vf, VTf);
    quant_f32d<<<3072, 256>>>(VTf, vt8a, vt8b, svt, 4096);

    // scores: fused dual int8 corrections (INIT S), then fp16 hi-pass RMW
    i8d_gemm<0><<<dim3(64, 32, 4), 256, I8D_SMEM>>>(
        q8h, q8l, k8l, k8h, sqh, sql, skl, skh, nullptr,
        S, nullptr, nullptr, 4096, 768,
        4096LL * 768, 4096LL * 768, 4096LL * 4096, 4096, 4096);
    wm_gemm<1, 2><<<dim3(32, 32, 4), 256, SMEM_TOTAL>>>(
        Qh, nullptr, Kh, nullptr, S, nullptr, nullptr, nullptr, nullptr,
        4096, 768, 4096LL * 768, 4096LL * 768, 4096LL * 4096);

    softmax_i8<<<16384, 256>>>(S, p8a, p8b, sp);

    // attn@V: double-level int8, pair out
    i8d_gemm<1><<<dim3(12, 32, 4), 256, I8D_SMEM>>>(
        p8a, p8b, vt8a, vt8b, sp, nullptr, svt, nullptr, nullptr,
        nullptr, NVh, NVl, 768, 4096,
        4096LL * 4096, 768LL * 4096, 4096LL * 768, 4096, 768);

    // FFN1: double-level int8 + bias + relu, pair out
    quant_pd<<<16384, 256>>>(NVh, NVl, nv8a, nv8b, snv, 768);
    i8d_gemm<2><<<dim3(48, 128, 1), 256, I8D_SMEM>>>(
        nv8a, nv8b, w18a, w18b, snv, nullptr, sw1, nullptr, b1,
        nullptr, Hh, Hl, 3072, 768, 0, 0, 0, 0, 0);

    // FFN2: double-level int8 + bias, fp32 out
    quant_pd<<<16384, 256>>>(Hh, Hl, h8a, h8b, sH, 3072);
    i8d_gemm<3><<<dim3(12, 128, 1), 256, I8D_SMEM>>>(
        h8a, h8b, w28a, w28b, sH, nullptr, sw2, nullptr, b2,
        out, nullptr, nullptr, 768, 3072, 0, 0, 0, 0, 0);
}

// round 15
// speedup vs baseline: 1.0178x; 1.0178x over previous
#include <cuda_runtime.h>
#include <cuda_fp16.h>
#include <stdint.h>

// ============================================================================
// GPT block, sm_100-safe mma.sync.
//   QKV      : fused 3-pass fp16 GEMM (Q,K pair out; V fp32 out)
//   scores   : ONE fused kernel: fp32acc Qh*Kh (fp16 MMA) + s32acc tied-scale
//              int8 corrections (q8h*k8l + q8l*k8h, lo scale = hi/2048)
//   attn@V / FFN1 / FFN2 : int8 double-level single kernels (R13 128x128)
// ============================================================================

typedef __half h16;

// ---------------- helpers ----------------
__device__ __forceinline__ uint32_t smem_u32(const void* p) {
    uint32_t a;
    asm("{ .reg .u64 t; cvta.to.shared.u64 t, %1; cvt.u32.u64 %0, t; }"
        : "=r"(a) : "l"(p));
    return a;
}
__device__ __forceinline__ void cp16(uint32_t saddr, const void* g) {
    asm volatile("cp.async.cg.shared.global [%0], [%1], 16;"
                 :: "r"(saddr), "l"(g) : "memory");
}
#define CP_COMMIT() asm volatile("cp.async.commit_group;" ::: "memory")
#define CP_WAIT1()  asm volatile("cp.async.wait_group 1;" ::: "memory")

__device__ __forceinline__ void ldsm4(uint32_t* r, uint32_t a) {
    asm volatile("ldmatrix.sync.aligned.m8n8.x4.shared.b16 {%0,%1,%2,%3}, [%4];"
                 : "=r"(r[0]), "=r"(r[1]), "=r"(r[2]), "=r"(r[3]) : "r"(a));
}
__device__ __forceinline__ void mma16816(float* c, const uint32_t* a,
                                         const uint32_t* b) {
    asm volatile(
        "mma.sync.aligned.m16n8k16.row.col.f32.f16.f16.f32 "
        "{%0,%1,%2,%3}, {%4,%5,%6,%7}, {%8,%9}, {%0,%1,%2,%3};"
        : "+f"(c[0]), "+f"(c[1]), "+f"(c[2]), "+f"(c[3])
        : "r"(a[0]), "r"(a[1]), "r"(a[2]), "r"(a[3]), "r"(b[0]), "r"(b[1]));
}
__device__ __forceinline__ void mma_s8(int* c, const uint32_t* a,
                                       const uint32_t* b) {
    asm volatile(
        "mma.sync.aligned.m16n8k32.row.col.s32.s8.s8.s32 "
        "{%0,%1,%2,%3}, {%4,%5,%6,%7}, {%8,%9}, {%0,%1,%2,%3};"
        : "+r"(c[0]), "+r"(c[1]), "+r"(c[2]), "+r"(c[3])
        : "r"(a[0]), "r"(a[1]), "r"(a[2]), "r"(a[3]), "r"(b[0]), "r"(b[1]));
}

__device__ __forceinline__ uint32_t swz(int r, int s) {
    return (uint32_t)(r * 64 + ((s ^ ((r >> 1) & 3)) << 4));
}
__device__ __forceinline__ void split2h(float v, h16& h, h16& l) {
    h = __float2half(v);
    l = __float2half(v - __half2float(h));
}
__device__ __forceinline__ int clamp127(int x) {
    return x < -127 ? -127 : (x > 127 ? 127 : x);
}

// ---------------- scratch ----------------
__device__ h16 g_Xh[16384LL * 768], g_Xl[16384LL * 768];
__device__ h16 g_Wch[2304LL * 768], g_Wcl[2304LL * 768];
__device__ h16 g_Qh[4LL * 4096 * 768], g_Ql[4LL * 4096 * 768];
__device__ h16 g_Kh[4LL * 4096 * 768], g_Kl[4LL * 4096 * 768];
__device__ float g_Vf[4LL * 4096 * 768];
__device__ float g_VTf[4LL * 768 * 4096];
__device__ float g_S[4LL * 4096 * 4096];
__device__ h16 g_NVh[4LL * 4096 * 768], g_NVl[4LL * 4096 * 768];
__device__ h16 g_Hh[16384LL * 3072], g_Hl[16384LL * 3072];
__device__ char g_q8h[16384LL * 768], g_q8l[16384LL * 768];
__device__ char g_k8h[16384LL * 768], g_k8l[16384LL * 768];
__device__ float g_sqh[16384], g_skh[16384];
__device__ char g_p8a[16384LL * 4096], g_p8b[16384LL * 4096];
__device__ char g_vt8a[3072LL * 4096], g_vt8b[3072LL * 4096];
__device__ char g_nv8a[16384LL * 768], g_nv8b[16384LL * 768];
__device__ char g_h8a[16384LL * 3072], g_h8b[16384LL * 3072];
__device__ char g_w18a[3072 * 768], g_w18b[3072 * 768];
__device__ char g_w28a[768 * 3072], g_w28b[768 * 3072];
__device__ float g_sp[16384], g_svt[3072], g_snv[16384], g_sH[16384];
__device__ float g_sw1[3072], g_sw2[768];

// ---------------- fp16 GEMM (QKV route) ----------------
static constexpr int STAGE_BYTES = 32768;
static constexpr int SMEM_TOTAL  = 3 * STAGE_BYTES;

__device__ __forceinline__ void load_stage3(
    uint32_t so, int tid,
    const h16* __restrict__ Ah, const h16* __restrict__ Al,
    const h16* __restrict__ Bh, const h16* __restrict__ Bl,
    long long k0, int K)
{
    const int r = tid & 127, h = tid >> 7;
#pragma unroll
    for (int u = 0; u < 2; ++u) {
        const uint32_t d = swz(r, h * 2 + u);
        const long long g = (long long)r * K + k0 + (h * 2 + u) * 8;
        cp16(so + d,         Ah + g);
        cp16(so + 8192 + d,  Al + g);
        cp16(so + 16384 + d, Bh + g);
        cp16(so + 24576 + d, Bl + g);
    }
}

// fused QKV: 3-pass fp16; Q,K pair out; V fp32 out
__global__ __launch_bounds__(256, 2)
void wm_gemm_qkv(const h16* __restrict__ Ahi, const h16* __restrict__ Alo,
                 const h16* __restrict__ Bhi, const h16* __restrict__ Blo,
                 float* __restrict__ Cf, h16* __restrict__ Chi, h16* __restrict__ Clo,
                 h16* __restrict__ C2hi, h16* __restrict__ C2lo,
                 const int N, const int K)
{
    extern __shared__ __align__(128) char smem[];
    const uint32_t sb = smem_u32(smem);
    const int tid = threadIdx.x;
    const int wid = tid >> 5, lane = tid & 31;
    const int wm = wid >> 1, wn = wid & 1;
    const int lj = lane >> 3, lr = lane & 7;

    const long long bm = (long long)blockIdx.y * 128;
    const long long bn = (long long)blockIdx.x * 128;

    const h16* Ah = Ahi + bm * K;
    const h16* Al = Alo + bm * K;
    const h16* Bh = Bhi + bn * K;
    const h16* Bl = Blo + bn * K;

    float acc[2][8][4];
#pragma unroll
    for (int i = 0; i < 2; ++i)
#pragma unroll
        for (int j = 0; j < 8; ++j)
#pragma unroll
            for (int t = 0; t < 4; ++t) acc[i][j][t] = 0.0f;

    const int NC = K / 32;
    load_stage3(sb, tid, Ah, Al, Bh, Bl, 0, K);
    CP_COMMIT();
    load_stage3(sb + STAGE_BYTES, tid, Ah, Al, Bh, Bl, 32, K);
    CP_COMMIT();

    const int arow = wm * 32 + ((lj & 1) << 3) + lr;
    const int aseg = lj >> 1;
    const int brow = wn * 64 + ((lj >> 1) << 3) + lr;
    const int bseg = lj & 1;

    int buf = 0;
    for (int c = 0; c < NC; ++c) {
        CP_WAIT1();
        __syncthreads();
        if (c + 2 < NC) {
            int nb = buf + 2; if (nb >= 3) nb -= 3;
            load_stage3(sb + nb * STAGE_BYTES, tid, Ah, Al, Bh, Bl,
                        (long long)(c + 2) * 32, K);
        }
        CP_COMMIT();

        const uint32_t bb = sb + buf * STAGE_BYTES;
#pragma unroll
        for (int ks = 0; ks < 2; ++ks) {
            uint32_t Afh[2][4], Afl[2][4];
#pragma unroll
            for (int mt = 0; mt < 2; ++mt) {
                const uint32_t off = swz(arow + mt * 16, ks * 2 + aseg);
                ldsm4(Afh[mt], bb + off);
                ldsm4(Afl[mt], bb + 8192 + off);
            }
#pragma unroll
            for (int ntp = 0; ntp < 4; ++ntp) {
                const uint32_t off = swz(brow + ntp * 16, ks * 2 + bseg);
                uint32_t Bfh[4], Bfl[4];
                ldsm4(Bfh, bb + 16384 + off);
                ldsm4(Bfl, bb + 24576 + off);
#pragma unroll
                for (int mt = 0; mt < 2; ++mt)
#pragma unroll
                    for (int h = 0; h < 2; ++h) {
                        float* cc = acc[mt][ntp * 2 + h];
                        mma16816(cc, Afh[mt], &Bfh[h * 2]);
                        mma16816(cc, Afl[mt], &Bfh[h * 2]);
                        mma16816(cc, Afh[mt], &Bfl[h * 2]);
                    }
            }
        }
        ++buf; if (buf == 3) buf = 0;
    }

    const int rbase = (int)bm + wm * 32 + (lane >> 2);
    const int seg   = (int)(bn / 768);
    const int cbase = (int)bn - seg * 768 + wn * 64 + (lane & 3) * 2;

#pragma unroll
    for (int mt = 0; mt < 2; ++mt)
#pragma unroll
        for (int nt = 0; nt < 8; ++nt) {
            const int col = cbase + nt * 8;
#pragma unroll
            for (int rh = 0; rh < 2; ++rh) {
                const int row = rbase + mt * 16 + rh * 8;
                const float v0 = acc[mt][nt][rh * 2 + 0];
                const float v1 = acc[mt][nt][rh * 2 + 1];
                const long long o = (long long)row * 768 + col;
                if (seg == 0) {
                    h16 h0, l0, h1, l1;
                    split2h(v0, h0, l0); split2h(v1, h1, l1);
                    *(__half2*)(Chi + o) = __halves2half2(h0, h1);
                    *(__half2*)(Clo + o) = __halves2half2(l0, l1);
                } else if (seg == 1) {
                    h16 h0, l0, h1, l1;
                    split2h(v0, h0, l0); split2h(v1, h1, l1);
                    *(__half2*)(C2hi + o) = __halves2half2(h0, h1);
                    *(__half2*)(C2lo + o) = __halves2half2(l0, l1);
                } else {
                    float2 w; w.x = v0; w.y = v1;
                    *(float2*)(Cf + o) = w;
                }
            }
        }
}

// ---------------- fused scores kernel ----------------
// S = Qh@Kh^T (fp16, fp32 acc) + sq_i*sk_j/2048 * (q8h@k8l^T + q8l@k8h^T) (s32)
// tiles 128x128, chunk k64, stage 64KB x3 = 192KB, 1 CTA/SM.
// stage: Qh0@0, Qh1@8192, Kh0@16384, Kh1@24576,
//        q8h@32768, q8l@40960, k8h@49152, k8l@57344
static constexpr int SF_STAGE = 65536;
static constexpr int SF_SMEM  = 3 * SF_STAGE;   // 196608

__device__ __forceinline__ void sf_load(uint32_t so, int tid,
    const h16* __restrict__ Qb, const h16* __restrict__ Kb,
    const char* __restrict__ qh, const char* __restrict__ ql,
    const char* __restrict__ kh, const char* __restrict__ kl,
    int k0)
{
    const int r = tid & 127, h = tid >> 7;
#pragma unroll
    for (int u = 0; u < 2; ++u) {
        const int s = h * 2 + u;
        const uint32_t d = swz(r, s);
        const long long gf = (long long)r * 768 + k0 + s * 8;   // fp16 elems
        cp16(so + d,         Qb + gf);
        cp16(so + 8192 + d,  Qb + gf + 32);
        cp16(so + 16384 + d, Kb + gf);
        cp16(so + 24576 + d, Kb + gf + 32);
        const long long gi = (long long)r * 768 + k0 + s * 16;  // int8 bytes
        cp16(so + 32768 + d, qh + gi);
        cp16(so + 40960 + d, ql + gi);
        cp16(so + 49152 + d, kh + gi);
        cp16(so + 57344 + d, kl + gi);
    }
}

__global__ __launch_bounds__(256, 1)
void scores_fused(const h16* __restrict__ Qh, const h16* __restrict__ Kh,
                  const char* __restrict__ q8h, const char* __restrict__ q8l,
                  const char* __restrict__ k8h, const char* __restrict__ k8l,
                  const float* __restrict__ sq, const float* __restrict__ sk,
                  float* __restrict__ S)
{
    extern __shared__ __align__(128) char smem[];
    const uint32_t sb = smem_u32(smem);
    const int tid = threadIdx.x;
    const int wid = tid >> 5, lane = tid & 31;
    const int wm = wid >> 1, wn = wid & 1;
    const int lj = lane >> 3, lr = lane & 7;
    const int z = blockIdx.z;
    const long long bm = (long long)blockIdx.y * 128;
    const long long bn = (long long)blockIdx.x * 128;

    const h16* Qb = Qh + (long long)z * 4096 * 768 + bm * 768;
    const h16* Kb = Kh + (long long)z * 4096 * 768 + bn * 768;
    const char* qhb = q8h + (long long)z * 4096 * 768 + bm * 768;
    const char* qlb = q8l + (long long)z * 4096 * 768 + bm * 768;
    const char* khb = k8h + (long long)z * 4096 * 768 + bn * 768;
    const char* klb = k8l + (long long)z * 4096 * 768 + bn * 768;

    float facc[2][8][4];
    int   iacc[2][8][4];
#pragma unroll
    for (int i = 0; i < 2; ++i)
#pragma unroll
        for (int j = 0; j < 8; ++j)
#pragma unroll
            for (int t = 0; t < 4; ++t) { facc[i][j][t] = 0.0f; iacc[i][j][t] = 0; }

    sf_load(sb, tid, Qb, Kb, qhb, qlb, khb, klb, 0);
    CP_COMMIT();
    sf_load(sb + SF_STAGE, tid, Qb, Kb, qhb, qlb, khb, klb, 64);
    CP_COMMIT();

    const int arow = wm * 32 + ((lj & 1) << 3) + lr;
    const int aseg = lj >> 1;
    const int brow = wn * 64 + ((lj >> 1) << 3) + lr;
    const int bseg = lj & 1;

    int buf = 0;
    for (int c = 0; c < 12; ++c) {      // 768/64
        CP_WAIT1();
        __syncthreads();
        if (c + 2 < 12) {
            int nb = buf + 2; if (nb >= 3) nb -= 3;
            sf_load(sb + nb * SF_STAGE, tid, Qb, Kb, qhb, qlb, khb, klb,
                    (c + 2) * 64);
        }
        CP_COMMIT();

        const uint32_t bb = sb + buf * SF_STAGE;
        // ---- fp16 hi: 2 subtiles x 2 k16-steps ----
#pragma unroll
        for (int sub = 0; sub < 2; ++sub) {
            const uint32_t qoff = bb + sub * 8192;
            const uint32_t koff = bb + 16384 + sub * 8192;
#pragma unroll
            for (int ks = 0; ks < 2; ++ks) {
                uint32_t Af[2][4];
#pragma unroll
                for (int mt = 0; mt < 2; ++mt)
                    ldsm4(Af[mt], qoff + swz(arow + mt * 16, ks * 2 + aseg));
#pragma unroll
                for (int ntp = 0; ntp < 4; ++ntp) {
                    uint32_t Bf[4];
                    ldsm4(Bf, koff + swz(brow + ntp * 16, ks * 2 + bseg));
#pragma unroll
                    for (int mt = 0; mt < 2; ++mt)
#pragma unroll
                        for (int h = 0; h < 2; ++h)
                            mma16816(facc[mt][ntp * 2 + h], Af[mt], &Bf[h * 2]);
                }
            }
        }
        // ---- int8 corrections: 2 k32-steps, ONE s32 acc (tied scale) ----
#pragma unroll
        for (int step = 0; step < 2; ++step) {
            uint32_t A1f[2][4], A2f[2][4];
#pragma unroll
            for (int mt = 0; mt < 2; ++mt) {
                const uint32_t off = swz(arow + mt * 16, step * 2 + aseg);
                ldsm4(A1f[mt], bb + 32768 + off);   // q8h
                ldsm4(A2f[mt], bb + 40960 + off);   // q8l (tied /2048)
            }
#pragma unroll
            for (int ntp = 0; ntp < 4; ++ntp) {
                const uint32_t off = swz(brow + ntp * 16, step * 2 + bseg);
                uint32_t B1f[4], B2f[4];
                ldsm4(B1f, bb + 49152 + off);       // k8h
                ldsm4(B2f, bb + 57344 + off);       // k8l (tied /2048)
#pragma unroll
                for (int mt = 0; mt < 2; ++mt)
#pragma unroll
                    for (int h = 0; h < 2; ++h) {
                        int* cc = iacc[mt][ntp * 2 + h];
                        mma_s8(cc, A1f[mt], &B2f[h * 2]);   // q8h * k8l
                        mma_s8(cc, A2f[mt], &B1f[h * 2]);   // q8l * k8h
                    }
            }
        }
        ++buf; if (buf == 3) buf = 0;
    }

    // epilogue: S = facc + sq*sk/2048 * iacc
    const int rb = wm * 32 + (lane >> 2);
    const int cb = wn * 64 + (lane & 3) * 2;
    const long long zS = (long long)z * 4096 * 4096;
    const float inv2048 = 4.8828125e-4f;   // 1/2048
#pragma unroll
    for (int mt = 0; mt < 2; ++mt)
#pragma unroll
        for (int rh = 0; rh < 2; ++rh) {
            const int lrw = rb + mt * 16 + rh * 8;
            const float sA = sq[(long long)z * 4096 + bm + lrw] * inv2048;
#pragma unroll
            for (int nt = 0; nt < 8; ++nt) {
                const int lc = cb + nt * 8;
                const float sB0 = sk[(long long)z * 4096 + bn + lc];
                const float sB1 = sk[(long long)z * 4096 + bn + lc + 1];
                float2 w;
                w.x = facc[mt][nt][rh * 2 + 0]
                    + sA * sB0 * (float)iacc[mt][nt][rh * 2 + 0];
                w.y = facc[mt][nt][rh * 2 + 1]
                    + sA * sB1 * (float)iacc[mt][nt][rh * 2 + 1];
                *(float2*)(S + zS + (bm + lrw) * 4096 + bn + lc) = w;
            }
        }
}

// ---------------- dual-acc double-level int8 GEMM (R13, 128x128) ----------
// MODE 1: val = sa1*sb1*(acc1 + acc2/256)         -> pair out
// MODE 2: + bias + relu                            -> pair out
// MODE 3: + bias                                   -> f32 out
static constexpr int I8D_STAGE = 32768;
static constexpr int I8D_SMEM  = 3 * I8D_STAGE;

__device__ __forceinline__ void i8d_load(uint32_t so, int tid,
    const char* __restrict__ A1, const char* __restrict__ A2,
    const char* __restrict__ B1, const char* __restrict__ B2,
    long long k0, int K)
{
    const int r = tid & 127, hf = tid >> 7;
#pragma unroll
    for (int u = 0; u < 2; ++u) {
        const int s = hf * 2 + u;
        const uint32_t d = swz(r, s);
        const long long g = (long long)r * K + k0 + s * 16;
        cp16(so + d,         A1 + g);
        cp16(so + 8192 + d,  A2 + g);
        cp16(so + 16384 + d, B1 + g);
        cp16(so + 24576 + d, B2 + g);
    }
}

template <int MODE>
__global__ __launch_bounds__(256, 1)
void i8d_gemm(const char* __restrict__ A1, const char* __restrict__ A2,
              const char* __restrict__ B1, const char* __restrict__ B2,
              const float* __restrict__ sa1, const float* __restrict__ sb1,
              const float* __restrict__ bias,
              float* __restrict__ Cf, h16* __restrict__ Chi, h16* __restrict__ Clo,
              const int N, const int K,
              const long long bA, const long long bB, const long long bC,
              const int sAz, const int sBz)
{
    extern __shared__ __align__(128) char smem[];
    const uint32_t sbase = smem_u32(smem);
    const int tid = threadIdx.x;
    const int wid = tid >> 5, lane = tid & 31;
    const int wm = wid >> 1, wn = wid & 1;
    const int lj = lane >> 3, lr = lane & 7;
    const int z = blockIdx.z;
    const long long bm = (long long)blockIdx.y * 128;
    const long long bn = (long long)blockIdx.x * 128;

    const char* A1b = A1 + (long long)z * bA + bm * K;
    const char* A2b = A2 + (long long)z * bA + bm * K;
    const char* B1b = B1 + (long long)z * bB + bn * K;
    const char* B2b = B2 + (long long)z * bB + bn * K;
    const float* sa1v = sa1 + (long long)z * sAz + bm;
    const float* sb1v = sb1 + (long long)z * sBz + bn;

    int acc1[2][8][4], acc2[2][8][4];
#pragma unroll
    for (int i = 0; i < 2; ++i)
#pragma unroll
        for (int j = 0; j < 8; ++j)
#pragma unroll
            for (int t = 0; t < 4; ++t) { acc1[i][j][t] = 0; acc2[i][j][t] = 0; }

    const int NC = K / 64;
    i8d_load(sbase, tid, A1b, A2b, B1b, B2b, 0, K);
    CP_COMMIT();
    i8d_load(sbase + I8D_STAGE, tid, A1b, A2b, B1b, B2b, 64, K);
    CP_COMMIT();

    const int arow = wm * 32 + ((lj & 1) << 3) + lr;
    const int aso  = lj >> 1;
    const int brow = wn * 64 + ((lj >> 1) << 3) + lr;
    const int bso  = lj & 1;

    int buf = 0;
    for (int c = 0; c < NC; ++c) {
        CP_WAIT1();
        __syncthreads();
        if (c + 2 < NC) {
            int nb = buf + 2; if (nb >= 3) nb -= 3;
            i8d_load(sbase + nb * I8D_STAGE, tid, A1b, A2b, B1b, B2b,
                     (long long)(c + 2) * 64, K);
        }
        CP_COMMIT();

        const uint32_t bb = sbase + buf * I8D_STAGE;
#pragma unroll
        for (int step = 0; step < 2; ++step) {
            uint32_t A1f[2][4], A2f[2][4];
#pragma unroll
            for (int mt = 0; mt < 2; ++mt) {
                const uint32_t off = swz(arow + mt * 16, step * 2 + aso);
                ldsm4(A1f[mt], bb + off);
                ldsm4(A2f[mt], bb + 8192 + off);
            }
#pragma unroll
            for (int ntp = 0; ntp < 4; ++ntp) {
                const uint32_t off = swz(brow + ntp * 16, step * 2 + bso);
                uint32_t B1f[4], B2f[4];
                ldsm4(B1f, bb + 16384 + off);
                ldsm4(B2f, bb + 24576 + off);
#pragma unroll
                for (int mt = 0; mt < 2; ++mt)
#pragma unroll
                    for (int h = 0; h < 2; ++h) {
                        int* c1 = acc1[mt][ntp * 2 + h];
                        int* c2 = acc2[mt][ntp * 2 + h];
                        mma_s8(c1, A1f[mt], &B1f[h * 2]);
                        mma_s8(c2, A1f[mt], &B2f[h * 2]);
                        mma_s8(c2, A2f[mt], &B1f[h * 2]);
                    }
            }
        }
        ++buf; if (buf == 3) buf = 0;
    }

    const int rb = wm * 32 + (lane >> 2);
    const int cb = wn * 64 + (lane & 3) * 2;
    const long long zC = (long long)z * bC;
#pragma unroll
    for (int mt = 0; mt < 2; ++mt)
#pragma unroll
        for (int rh = 0; rh < 2; ++rh) {
            const int lrw = rb + mt * 16 + rh * 8;
            const float sA1 = sa1v[lrw];
#pragma unroll
            for (int nt = 0; nt < 8; ++nt) {
                const int lc = cb + nt * 8;
                const int x1a = acc1[mt][nt][rh * 2 + 0];
                const int x1b = acc1[mt][nt][rh * 2 + 1];
                const int x2a = acc2[mt][nt][rh * 2 + 0];
                const int x2b = acc2[mt][nt][rh * 2 + 1];
                float v0 = sA1 * sb1v[lc]
                         * ((float)x1a + (float)x2a * 0.00390625f);
                float v1 = sA1 * sb1v[lc + 1]
                         * ((float)x1b + (float)x2b * 0.00390625f);
                if (MODE >= 2) {
                    v0 += bias[(int)bn + lc];
                    v1 += bias[(int)bn + lc + 1];
                }
                if (MODE == 2) { v0 = fmaxf(v0, 0.f); v1 = fmaxf(v1, 0.f); }
                const long long o = zC + (bm + lrw) * N + bn + lc;
                if (MODE == 3) {
                    float2 w; w.x = v0; w.y = v1;
                    *(float2*)(Cf + o) = w;
                } else {
                    h16 h0, l0, h1, l1;
                    split2h(v0, h0, l0); split2h(v1, h1, l1);
                    *(__half2*)(Chi + o) = __halves2half2(h0, h1);
                    *(__half2*)(Clo + o) = __halves2half2(l0, l1);
                }
            }
        }
}

// -------- per-row int8 quant of fp16 pair, L=768; lo tied at hi/2048 --------
__global__ __launch_bounds__(256)
void quant_rows(const h16* __restrict__ Ah, const h16* __restrict__ Al,
                char* __restrict__ q8h, char* __restrict__ q8l,
                float* __restrict__ sh)
{
    __shared__ float red[8];
    const long long row = blockIdx.x;
    const int tid = threadIdx.x, lane = tid & 31, warp = tid >> 5;
    const h16* ph = Ah + row * 768;
    const h16* pl = Al + row * 768;

    float vh[3], vl[3];
    float mh = 0.f;
#pragma unroll
    for (int i = 0; i < 3; ++i) {
        vh[i] = __half2float(ph[tid + i * 256]);
        vl[i] = __half2float(pl[tid + i * 256]);
        mh = fmaxf(mh, fabsf(vh[i]));
    }
#pragma unroll
    for (int o = 16; o > 0; o >>= 1)
        mh = fmaxf(mh, __shfl_xor_sync(0xffffffffu, mh, o));
    if (lane == 0) red[warp] = mh;
    __syncthreads();
    mh = red[0];
#pragma unroll
    for (int w = 1; w < 8; ++w) mh = fmaxf(mh, red[w]);
    mh = fmaxf(mh, 1e-20f);
    const float ih = 127.f / mh;
    const float il = ih * 2048.f;     // tied lo scale = hi/2048
#pragma unroll
    for (int i = 0; i < 3; ++i) {
        q8h[row * 768 + tid + i * 256] = (char)__float2int_rn(vh[i] * ih);
        q8l[row * 768 + tid + i * 256] =
            (char)clamp127(__float2int_rn(vl[i] * il));
    }
    if (tid == 0) sh[row] = mh / 127.f;
}

// ---------------- per-row double-level quant of fp16 pair ----------------
__global__ __launch_bounds__(256)
void quant_pd(const h16* __restrict__ Ah, const h16* __restrict__ Al,
              char* __restrict__ q1, char* __restrict__ q2,
              float* __restrict__ s, const int L)
{
    __shared__ float red[8];
    const long long row = blockIdx.x;
    const int tid = threadIdx.x, lane = tid & 31, warp = tid >> 5;
    const h16* ph = Ah + row * (long long)L;
    const h16* pl = Al + row * (long long)L;

    float m = 0.f;
    for (int i = tid; i < L; i += 256)
        m = fmaxf(m, fabsf(__half2float(ph[i]) + __half2float(pl[i])));
#pragma unroll
    for (int o = 16; o > 0; o >>= 1)
        m = fmaxf(m, __shfl_xor_sync(0xffffffffu, m, o));
    if (lane == 0) red[warp] = m;
    __syncthreads();
    m = red[0];
#pragma unroll
    for (int w = 1; w < 8; ++w) m = fmaxf(m, red[w]);
    m = fmaxf(m, 1e-20f);
    const float inv = 127.f / m;
    char* p1 = q1 + row * (long long)L;
    char* p2 = q2 + row * (long long)L;
    for (int i = tid; i < L; i += 256) {
        const float v = (__half2float(ph[i]) + __half2float(pl[i])) * inv;
        const int a = __float2int_rn(v);
        p1[i] = (char)a;
        p2[i] = (char)clamp127(__float2int_rn((v - (float)a) * 256.f));
    }
    if (tid == 0) s[row] = m / 127.f;
}

// ---------------- per-row double-level quant of fp32 rows ----------------
__global__ __launch_bounds__(256)
void quant_f32d(const float* __restrict__ A, char* __restrict__ q1,
                char* __restrict__ q2, float* __restrict__ s, const int L)
{
    __shared__ float red[8];
    const long long row = blockIdx.x;
    const int tid = threadIdx.x, lane = tid & 31, warp = tid >> 5;
    const float* p = A + row * (long long)L;

    float m = 0.f;
    for (int i = tid; i < L; i += 256)
        m = fmaxf(m, fabsf(p[i]));
#pragma unroll
    for (int o = 16; o > 0; o >>= 1)
        m = fmaxf(m, __shfl_xor_sync(0xffffffffu, m, o));
    if (lane == 0) red[warp] = m;
    __syncthreads();
    m = red[0];
#pragma unroll
    for (int w = 1; w < 8; ++w) m = fmaxf(m, red[w]);
    m = fmaxf(m, 1e-20f);
    const float inv = 127.f / m;
    char* p1 = q1 + row * (long long)L;
    char* p2 = q2 + row * (long long)L;
    for (int i = tid; i < L; i += 256) {
        const float v = p[i] * inv;
        const int a = __float2int_rn(v);
        p1[i] = (char)a;
        p2[i] = (char)clamp127(__float2int_rn((v - (float)a) * 256.f));
    }
    if (tid == 0) s[row] = m / 127.f;
}

// ---------------- fp32 -> (hi,lo) fp16 ----------------
__global__ __launch_bounds__(256)
void cvt_pair(const float* __restrict__ in, h16* __restrict__ hi,
              h16* __restrict__ lo, const long long n)
{
    const long long i = ((long long)blockIdx.x * 256 + threadIdx.x) * 4;
    if (i >= n) return;
    const float4 v = *(const float4*)(in + i);
    __align__(8) h16 h[4];
    __align__(8) h16 l[4];
    split2h(v.x, h[0], l[0]); split2h(v.y, h[1], l[1]);
    split2h(v.z, h[2], l[2]); split2h(v.w, h[3], l[3]);
    *(uint2*)(hi + i) = *(const uint2*)h;
    *(uint2*)(lo + i) = *(const uint2*)l;
}

// ---------------- V transpose: [b,4096,768]f32 -> [b,768,4096] fp32 ----------
__global__ __launch_bounds__(256)
void transpose_f32(const float* __restrict__ V, float* __restrict__ T)
{
    __shared__ float tile[32][33];
    const int b = blockIdx.z;
    const int e0 = blockIdx.x * 32;
    const int t0 = blockIdx.y * 32;
    const float* Vb = V + (long long)b * 4096 * 768;
    float* Tb = T + (long long)b * 768 * 4096;
    const int tx = threadIdx.x, ty = threadIdx.y;
#pragma unroll
    for (int j = 0; j < 32; j += 8)
        tile[ty + j][tx] = Vb[(long long)(t0 + ty + j) * 768 + e0 + tx];
    __syncthreads();
#pragma unroll
    for (int j = 0; j < 32; j += 8)
        Tb[(long long)(e0 + ty + j) * 4096 + t0 + tx] = tile[tx][ty + j];
}

// ---------------- softmax (rows of 4096) -> double-level int8 ----------------
__global__ __launch_bounds__(256)
void softmax_i8(const float* __restrict__ S, char* __restrict__ p8a,
                char* __restrict__ p8b, float* __restrict__ sp)
{
    __shared__ float red[8];
    const long long row = blockIdx.x;
    const float* p = S + row * 4096;
    const int tid = threadIdx.x, lane = tid & 31, warp = tid >> 5;

    float4 v[4];
#pragma unroll
    for (int i = 0; i < 4; ++i)
        v[i] = *(const float4*)(p + tid * 4 + i * 1024);

    float mx = -3.402823466e38f;
#pragma unroll
    for (int i = 0; i < 4; ++i)
        mx = fmaxf(mx, fmaxf(fmaxf(v[i].x, v[i].y), fmaxf(v[i].z, v[i].w)));
#pragma unroll
    for (int o = 16; o > 0; o >>= 1)
        mx = fmaxf(mx, __shfl_xor_sync(0xffffffffu, mx, o));
    if (lane == 0) red[warp] = mx;
    __syncthreads();
    float rowmax = red[0];
#pragma unroll
    for (int w = 1; w < 8; ++w) rowmax = fmaxf(rowmax, red[w]);
    __syncthreads();

    float sum = 0.0f;
#pragma unroll
    for (int i = 0; i < 4; ++i) {
        v[i].x = __expf(v[i].x - rowmax);
        v[i].y = __expf(v[i].y - rowmax);
        v[i].z = __expf(v[i].z - rowmax);
        v[i].w = __expf(v[i].w - rowmax);
        sum += (v[i].x + v[i].y) + (v[i].z + v[i].w);
    }
#pragma unroll
    for (int o = 16; o > 0; o >>= 1)
        sum += __shfl_xor_sync(0xffffffffu, sum, o);
    if (lane == 0) red[warp] = sum;
    __syncthreads();
    float rowsum = 0.0f;
#pragma unroll
    for (int w = 0; w < 8; ++w) rowsum += red[w];

#pragma unroll
    for (int i = 0; i < 4; ++i) {
        int q1[4], q2[4];
        const float e[4] = {v[i].x, v[i].y, v[i].z, v[i].w};
#pragma unroll
        for (int t = 0; t < 4; ++t) {
            const float u = 127.f * e[t];
            q1[t] = __float2int_rn(u);
            q2[t] = clamp127(__float2int_rn((u - (float)q1[t]) * 256.f));
        }
        const long long o = row * 4096 + tid * 4 + i * 1024;
        uint32_t w1 = ((uint32_t)(uint8_t)(char)q1[0])
                    | ((uint32_t)(uint8_t)(char)q1[1] << 8)
                    | ((uint32_t)(uint8_t)(char)q1[2] << 16)
                    | ((uint32_t)(uint8_t)(char)q1[3] << 24);
        uint32_t w2 = ((uint32_t)(uint8_t)(char)q2[0])
                    | ((uint32_t)(uint8_t)(char)q2[1] << 8)
                    | ((uint32_t)(uint8_t)(char)q2[2] << 16)
                    | ((uint32_t)(uint8_t)(char)q2[3] << 24);
        *(uint32_t*)(p8a + o) = w1;
        *(uint32_t*)(p8b + o) = w2;
    }
    if (tid == 0) sp[row] = (1.0f / rowsum) / 127.f;
}

// ---------------- host ----------------
extern "C" void kernel_launch(void* const* d_in, const int* in_sizes, int n_in,
                              void* d_out, int out_size)
{
    const float* X  = (const float*)d_in[0];
    const float* Wq = (const float*)d_in[1];
    const float* Wk = (const float*)d_in[2];
    const float* Wv = (const float*)d_in[3];
    const float* W1 = (const float*)d_in[4];
    const float* b1 = (const float*)d_in[5];
    const float* W2 = (const float*)d_in[6];
    const float* b2 = (const float*)d_in[7];
    float* out = (float*)d_out;

    h16 *Xh, *Xl, *Wch, *Wcl, *Qh, *Ql, *Kh, *Kl, *NVh, *NVl, *Hh, *Hl;
    float *Vf, *VTf, *S;
    char *q8h, *q8l, *k8h, *k8l;
    float *sqh, *skh;
    char *p8a, *p8b, *vt8a, *vt8b, *nv8a, *nv8b, *h8a, *h8b;
    char *w18a, *w18b, *w28a, *w28b;
    float *sp, *svt, *snv, *sH, *sw1, *sw2;
    cudaGetSymbolAddress((void**)&Xh, g_Xh);     cudaGetSymbolAddress((void**)&Xl, g_Xl);
    cudaGetSymbolAddress((void**)&Wch, g_Wch);   cudaGetSymbolAddress((void**)&Wcl, g_Wcl);
    cudaGetSymbolAddress((void**)&Qh, g_Qh);     cudaGetSymbolAddress((void**)&Ql, g_Ql);
    cudaGetSymbolAddress((void**)&Kh, g_Kh);     cudaGetSymbolAddress((void**)&Kl, g_Kl);
    cudaGetSymbolAddress((void**)&Vf, g_Vf);     cudaGetSymbolAddress((void**)&VTf, g_VTf);
    cudaGetSymbolAddress((void**)&S, g_S);
    cudaGetSymbolAddress((void**)&NVh, g_NVh);   cudaGetSymbolAddress((void**)&NVl, g_NVl);
    cudaGetSymbolAddress((void**)&Hh, g_Hh);     cudaGetSymbolAddress((void**)&Hl, g_Hl);
    cudaGetSymbolAddress((void**)&q8h, g_q8h);   cudaGetSymbolAddress((void**)&q8l, g_q8l);
    cudaGetSymbolAddress((void**)&k8h, g_k8h);   cudaGetSymbolAddress((void**)&k8l, g_k8l);
    cudaGetSymbolAddress((void**)&sqh, g_sqh);   cudaGetSymbolAddress((void**)&skh, g_skh);
    cudaGetSymbolAddress((void**)&p8a, g_p8a);   cudaGetSymbolAddress((void**)&p8b, g_p8b);
    cudaGetSymbolAddress((void**)&vt8a, g_vt8a); cudaGetSymbolAddress((void**)&vt8b, g_vt8b);
    cudaGetSymbolAddress((void**)&nv8a, g_nv8a); cudaGetSymbolAddress((void**)&nv8b, g_nv8b);
    cudaGetSymbolAddress((void**)&h8a, g_h8a);   cudaGetSymbolAddress((void**)&h8b, g_h8b);
    cudaGetSymbolAddress((void**)&w18a, g_w18a); cudaGetSymbolAddress((void**)&w18b, g_w18b);
    cudaGetSymbolAddress((void**)&w28a, g_w28a); cudaGetSymbolAddress((void**)&w28b, g_w28b);
    cudaGetSymbolAddress((void**)&sp, g_sp);     cudaGetSymbolAddress((void**)&svt, g_svt);
    cudaGetSymbolAddress((void**)&snv, g_snv);   cudaGetSymbolAddress((void**)&sH, g_sH);
    cudaGetSymbolAddress((void**)&sw1, g_sw1);   cudaGetSymbolAddress((void**)&sw2, g_sw2);

    cudaFuncSetAttribute(wm_gemm_qkv,
                         cudaFuncAttributeMaxDynamicSharedMemorySize, SMEM_TOTAL);
    cudaFuncSetAttribute(scores_fused,
                         cudaFuncAttributeMaxDynamicSharedMemorySize, SF_SMEM);
    cudaFuncSetAttribute(i8d_gemm<1>,
                         cudaFuncAttributeMaxDynamicSharedMemorySize, I8D_SMEM);
    cudaFuncSetAttribute(i8d_gemm<2>,
                         cudaFuncAttributeMaxDynamicSharedMemorySize, I8D_SMEM);
    cudaFuncSetAttribute(i8d_gemm<3>,
                         cudaFuncAttributeMaxDynamicSharedMemorySize, I8D_SMEM);

    // launches 0-4 (launch #5 = QKV GEMM for the ncu window)
    cvt_pair<<<12288, 256>>>(X,  Xh,  Xl,  16384LL * 768);
    cvt_pair<<<576,  256>>>(Wq, Wch,              Wcl,              768LL * 768);
    cvt_pair<<<576,  256>>>(Wk, Wch + 768 * 768,  Wcl + 768 * 768,  768LL * 768);
    cvt_pair<<<576,  256>>>(Wv, Wch + 1536 * 768, Wcl + 1536 * 768, 768LL * 768);
    quant_f32d<<<3072, 256>>>(W1, w18a, w18b, sw1, 768);

    // fused QKV: Q,K pair out; V fp32 out
    wm_gemm_qkv<<<dim3(18, 128, 1), 256, SMEM_TOTAL>>>(
        Xh, Xl, Wch, Wcl, Vf, Qh, Ql, Kh, Kl, 2304, 768);

    quant_rows<<<16384, 256>>>(Qh, Ql, q8h, q8l, sqh);
    quant_rows<<<16384, 256>>>(Kh, Kl, k8h, k8l, skh);
    quant_f32d<<<768, 256>>>(W2, w28a, w28b, sw2, 3072);
    transpose_f32<<<dim3(24, 128, 4), dim3(32, 8)>>>(Vf, VTf);
    quant_f32d<<<3072, 256>>>(VTf, vt8a, vt8b, svt, 4096);

    // scores: single fused kernel writes S once
    scores_fused<<<dim3(32, 32, 4), 256, SF_SMEM>>>(
        Qh, Kh, q8h, q8l, k8h, k8l, sqh, skh, S);

    softmax_i8<<<16384, 256>>>(S, p8a, p8b, sp);

    // attn@V: double-level int8, pair out
    i8d_gemm<1><<<dim3(6, 32, 4), 256, I8D_SMEM>>>(
        p8a, p8b, vt8a, vt8b, sp, svt, nullptr,
        nullptr, NVh, NVl, 768, 4096,
        4096LL * 4096, 768LL * 4096, 4096LL * 768, 4096, 768);

    // FFN1: double-level int8 + bias + relu, pair out
    quant_pd<<<16384, 256>>>(NVh, NVl, nv8a, nv8b, snv, 768);
    i8d_gemm<2><<<dim3(24, 128, 1), 256, I8D_SMEM>>>(
        nv8a, nv8b, w18a, w18b, snv, sw1, b1,
        nullptr, Hh, Hl, 3072, 768, 0, 0, 0, 0, 0);

    // FFN2: double-level int8 + bias, fp32 out
    quant_pd<<<16384, 256>>>(Hh, Hl, h8a, h8b, sH, 3072);
    i8d_gemm<3><<<dim3(6, 128, 1), 256, I8D_SMEM>>>(
        h8a, h8b, w28a, w28b, sH, sw2, b2,
        out, nullptr, nullptr, 768, 3072, 0, 0, 0, 0, 0);
}

// round 16
// speedup vs baseline: 1.0263x; 1.0084x over previous
#include <cuda_runtime.h>
#include <cuda_fp16.h>
#include <stdint.h>

// ============================================================================
// GPT block, sm_100-safe mma.sync.
//   QKV      : fused 3-pass fp16 GEMM (Q,K pair out; V fp32 out)
//   scores   : ONE fused kernel: fp32acc Qh*Kh + s32acc tied-scale int8 corr
//   attn@V / FFN1 / FFN2 : int8 double-level single kernels (128x128)
// R16: warp-per-row vectorized quant kernels; merged launches.
// ============================================================================

typedef __half h16;

// ---------------- helpers ----------------
__device__ __forceinline__ uint32_t smem_u32(const void* p) {
    uint32_t a;
    asm("{ .reg .u64 t; cvta.to.shared.u64 t, %1; cvt.u32.u64 %0, t; }"
        : "=r"(a) : "l"(p));
    return a;
}
__device__ __forceinline__ void cp16(uint32_t saddr, const void* g) {
    asm volatile("cp.async.cg.shared.global [%0], [%1], 16;"
                 :: "r"(saddr), "l"(g) : "memory");
}
#define CP_COMMIT() asm volatile("cp.async.commit_group;" ::: "memory")
#define CP_WAIT1()  asm volatile("cp.async.wait_group 1;" ::: "memory")

__device__ __forceinline__ void ldsm4(uint32_t* r, uint32_t a) {
    asm volatile("ldmatrix.sync.aligned.m8n8.x4.shared.b16 {%0,%1,%2,%3}, [%4];"
                 : "=r"(r[0]), "=r"(r[1]), "=r"(r[2]), "=r"(r[3]) : "r"(a));
}
__device__ __forceinline__ void mma16816(float* c, const uint32_t* a,
                                         const uint32_t* b) {
    asm volatile(
        "mma.sync.aligned.m16n8k16.row.col.f32.f16.f16.f32 "
        "{%0,%1,%2,%3}, {%4,%5,%6,%7}, {%8,%9}, {%0,%1,%2,%3};"
        : "+f"(c[0]), "+f"(c[1]), "+f"(c[2]), "+f"(c[3])
        : "r"(a[0]), "r"(a[1]), "r"(a[2]), "r"(a[3]), "r"(b[0]), "r"(b[1]));
}
__device__ __forceinline__ void mma_s8(int* c, const uint32_t* a,
                                       const uint32_t* b) {
    asm volatile(
        "mma.sync.aligned.m16n8k32.row.col.s32.s8.s8.s32 "
        "{%0,%1,%2,%3}, {%4,%5,%6,%7}, {%8,%9}, {%0,%1,%2,%3};"
        : "+r"(c[0]), "+r"(c[1]), "+r"(c[2]), "+r"(c[3])
        : "r"(a[0]), "r"(a[1]), "r"(a[2]), "r"(a[3]), "r"(b[0]), "r"(b[1]));
}

__device__ __forceinline__ uint32_t swz(int r, int s) {
    return (uint32_t)(r * 64 + ((s ^ ((r >> 1) & 3)) << 4));
}
__device__ __forceinline__ void split2h(float v, h16& h, h16& l) {
    h = __float2half(v);
    l = __float2half(v - __half2float(h));
}
__device__ __forceinline__ int clamp127(int x) {
    return x < -127 ? -127 : (x > 127 ? 127 : x);
}
__device__ __forceinline__ float warp_max(float m) {
#pragma unroll
    for (int o = 16; o > 0; o >>= 1)
        m = fmaxf(m, __shfl_xor_sync(0xffffffffu, m, o));
    return m;
}
__device__ __forceinline__ uint32_t pack4(int b0, int b1, int b2, int b3) {
    return (uint32_t)(uint8_t)b0 | ((uint32_t)(uint8_t)b1 << 8)
         | ((uint32_t)(uint8_t)b2 << 16) | ((uint32_t)(uint8_t)b3 << 24);
}

// ---------------- scratch ----------------
__device__ h16 g_Xh[16384LL * 768], g_Xl[16384LL * 768];
__device__ h16 g_Wch[2304LL * 768], g_Wcl[2304LL * 768];
__device__ h16 g_Qh[4LL * 4096 * 768], g_Ql[4LL * 4096 * 768];
__device__ h16 g_Kh[4LL * 4096 * 768], g_Kl[4LL * 4096 * 768];
__device__ float g_Vf[4LL * 4096 * 768];
__device__ float g_VTf[4LL * 768 * 4096];
__device__ float g_S[4LL * 4096 * 4096];
__device__ h16 g_NVh[4LL * 4096 * 768], g_NVl[4LL * 4096 * 768];
__device__ h16 g_Hh[16384LL * 3072], g_Hl[16384LL * 3072];
__device__ char g_q8h[16384LL * 768], g_q8l[16384LL * 768];
__device__ char g_k8h[16384LL * 768], g_k8l[16384LL * 768];
__device__ float g_sqh[16384], g_skh[16384];
__device__ char g_p8a[16384LL * 4096], g_p8b[16384LL * 4096];
__device__ char g_vt8a[3072LL * 4096], g_vt8b[3072LL * 4096];
__device__ char g_nv8a[16384LL * 768], g_nv8b[16384LL * 768];
__device__ char g_h8a[16384LL * 3072], g_h8b[16384LL * 3072];
__device__ char g_w18a[3072 * 768], g_w18b[3072 * 768];
__device__ char g_w28a[768 * 3072], g_w28b[768 * 3072];
__device__ float g_sp[16384], g_svt[3072], g_snv[16384], g_sH[16384];
__device__ float g_sw1[3072], g_sw2[768];

// ---------------- fp16 GEMM (QKV route) ----------------
static constexpr int STAGE_BYTES = 32768;
static constexpr int SMEM_TOTAL  = 3 * STAGE_BYTES;

__device__ __forceinline__ void load_stage3(
    uint32_t so, int tid,
    const h16* __restrict__ Ah, const h16* __restrict__ Al,
    const h16* __restrict__ Bh, const h16* __restrict__ Bl,
    long long k0, int K)
{
    const int r = tid & 127, h = tid >> 7;
#pragma unroll
    for (int u = 0; u < 2; ++u) {
        const uint32_t d = swz(r, h * 2 + u);
        const long long g = (long long)r * K + k0 + (h * 2 + u) * 8;
        cp16(so + d,         Ah + g);
        cp16(so + 8192 + d,  Al + g);
        cp16(so + 16384 + d, Bh + g);
        cp16(so + 24576 + d, Bl + g);
    }
}

__global__ __launch_bounds__(256, 2)
void wm_gemm_qkv(const h16* __restrict__ Ahi, const h16* __restrict__ Alo,
                 const h16* __restrict__ Bhi, const h16* __restrict__ Blo,
                 float* __restrict__ Cf, h16* __restrict__ Chi, h16* __restrict__ Clo,
                 h16* __restrict__ C2hi, h16* __restrict__ C2lo,
                 const int N, const int K)
{
    extern __shared__ __align__(128) char smem[];
    const uint32_t sb = smem_u32(smem);
    const int tid = threadIdx.x;
    const int wid = tid >> 5, lane = tid & 31;
    const int wm = wid >> 1, wn = wid & 1;
    const int lj = lane >> 3, lr = lane & 7;

    const long long bm = (long long)blockIdx.y * 128;
    const long long bn = (long long)blockIdx.x * 128;

    const h16* Ah = Ahi + bm * K;
    const h16* Al = Alo + bm * K;
    const h16* Bh = Bhi + bn * K;
    const h16* Bl = Blo + bn * K;

    float acc[2][8][4];
#pragma unroll
    for (int i = 0; i < 2; ++i)
#pragma unroll
        for (int j = 0; j < 8; ++j)
#pragma unroll
            for (int t = 0; t < 4; ++t) acc[i][j][t] = 0.0f;

    const int NC = K / 32;
    load_stage3(sb, tid, Ah, Al, Bh, Bl, 0, K);
    CP_COMMIT();
    load_stage3(sb + STAGE_BYTES, tid, Ah, Al, Bh, Bl, 32, K);
    CP_COMMIT();

    const int arow = wm * 32 + ((lj & 1) << 3) + lr;
    const int aseg = lj >> 1;
    const int brow = wn * 64 + ((lj >> 1) << 3) + lr;
    const int bseg = lj & 1;

    int buf = 0;
    for (int c = 0; c < NC; ++c) {
        CP_WAIT1();
        __syncthreads();
        if (c + 2 < NC) {
            int nb = buf + 2; if (nb >= 3) nb -= 3;
            load_stage3(sb + nb * STAGE_BYTES, tid, Ah, Al, Bh, Bl,
                        (long long)(c + 2) * 32, K);
        }
        CP_COMMIT();

        const uint32_t bb = sb + buf * STAGE_BYTES;
#pragma unroll
        for (int ks = 0; ks < 2; ++ks) {
            uint32_t Afh[2][4], Afl[2][4];
#pragma unroll
            for (int mt = 0; mt < 2; ++mt) {
                const uint32_t off = swz(arow + mt * 16, ks * 2 + aseg);
                ldsm4(Afh[mt], bb + off);
                ldsm4(Afl[mt], bb + 8192 + off);
            }
#pragma unroll
            for (int ntp = 0; ntp < 4; ++ntp) {
                const uint32_t off = swz(brow + ntp * 16, ks * 2 + bseg);
                uint32_t Bfh[4], Bfl[4];
                ldsm4(Bfh, bb + 16384 + off);
                ldsm4(Bfl, bb + 24576 + off);
#pragma unroll
                for (int mt = 0; mt < 2; ++mt)
#pragma unroll
                    for (int h = 0; h < 2; ++h) {
                        float* cc = acc[mt][ntp * 2 + h];
                        mma16816(cc, Afh[mt], &Bfh[h * 2]);
                        mma16816(cc, Afl[mt], &Bfh[h * 2]);
                        mma16816(cc, Afh[mt], &Bfl[h * 2]);
                    }
            }
        }
        ++buf; if (buf == 3) buf = 0;
    }

    const int rbase = (int)bm + wm * 32 + (lane >> 2);
    const int seg   = (int)(bn / 768);
    const int cbase = (int)bn - seg * 768 + wn * 64 + (lane & 3) * 2;

#pragma unroll
    for (int mt = 0; mt < 2; ++mt)
#pragma unroll
        for (int nt = 0; nt < 8; ++nt) {
            const int col = cbase + nt * 8;
#pragma unroll
            for (int rh = 0; rh < 2; ++rh) {
                const int row = rbase + mt * 16 + rh * 8;
                const float v0 = acc[mt][nt][rh * 2 + 0];
                const float v1 = acc[mt][nt][rh * 2 + 1];
                const long long o = (long long)row * 768 + col;
                if (seg == 0) {
                    h16 h0, l0, h1, l1;
                    split2h(v0, h0, l0); split2h(v1, h1, l1);
                    *(__half2*)(Chi + o) = __halves2half2(h0, h1);
                    *(__half2*)(Clo + o) = __halves2half2(l0, l1);
                } else if (seg == 1) {
                    h16 h0, l0, h1, l1;
                    split2h(v0, h0, l0); split2h(v1, h1, l1);
                    *(__half2*)(C2hi + o) = __halves2half2(h0, h1);
                    *(__half2*)(C2lo + o) = __halves2half2(l0, l1);
                } else {
                    float2 w; w.x = v0; w.y = v1;
                    *(float2*)(Cf + o) = w;
                }
            }
        }
}

// ---------------- fused scores kernel ----------------
static constexpr int SF_STAGE = 65536;
static constexpr int SF_SMEM  = 3 * SF_STAGE;

__device__ __forceinline__ void sf_load(uint32_t so, int tid,
    const h16* __restrict__ Qb, const h16* __restrict__ Kb,
    const char* __restrict__ qh, const char* __restrict__ ql,
    const char* __restrict__ kh, const char* __restrict__ kl,
    int k0)
{
    const int r = tid & 127, h = tid >> 7;
#pragma unroll
    for (int u = 0; u < 2; ++u) {
        const int s = h * 2 + u;
        const uint32_t d = swz(r, s);
        const long long gf = (long long)r * 768 + k0 + s * 8;
        cp16(so + d,         Qb + gf);
        cp16(so + 8192 + d,  Qb + gf + 32);
        cp16(so + 16384 + d, Kb + gf);
        cp16(so + 24576 + d, Kb + gf + 32);
        const long long gi = (long long)r * 768 + k0 + s * 16;
        cp16(so + 32768 + d, qh + gi);
        cp16(so + 40960 + d, ql + gi);
        cp16(so + 49152 + d, kh + gi);
        cp16(so + 57344 + d, kl + gi);
    }
}

__global__ __launch_bounds__(256, 1)
void scores_fused(const h16* __restrict__ Qh, const h16* __restrict__ Kh,
                  const char* __restrict__ q8h, const char* __restrict__ q8l,
                  const char* __restrict__ k8h, const char* __restrict__ k8l,
                  const float* __restrict__ sq, const float* __restrict__ sk,
                  float* __restrict__ S)
{
    extern __shared__ __align__(128) char smem[];
    const uint32_t sb = smem_u32(smem);
    const int tid = threadIdx.x;
    const int wid = tid >> 5, lane = tid & 31;
    const int wm = wid >> 1, wn = wid & 1;
    const int lj = lane >> 3, lr = lane & 7;
    const int z = blockIdx.z;
    const long long bm = (long long)blockIdx.y * 128;
    const long long bn = (long long)blockIdx.x * 128;

    const h16* Qb = Qh + (long long)z * 4096 * 768 + bm * 768;
    const h16* Kb = Kh + (long long)z * 4096 * 768 + bn * 768;
    const char* qhb = q8h + (long long)z * 4096 * 768 + bm * 768;
    const char* qlb = q8l + (long long)z * 4096 * 768 + bm * 768;
    const char* khb = k8h + (long long)z * 4096 * 768 + bn * 768;
    const char* klb = k8l + (long long)z * 4096 * 768 + bn * 768;

    float facc[2][8][4];
    int   iacc[2][8][4];
#pragma unroll
    for (int i = 0; i < 2; ++i)
#pragma unroll
        for (int j = 0; j < 8; ++j)
#pragma unroll
            for (int t = 0; t < 4; ++t) { facc[i][j][t] = 0.0f; iacc[i][j][t] = 0; }

    sf_load(sb, tid, Qb, Kb, qhb, qlb, khb, klb, 0);
    CP_COMMIT();
    sf_load(sb + SF_STAGE, tid, Qb, Kb, qhb, qlb, khb, klb, 64);
    CP_COMMIT();

    const int arow = wm * 32 + ((lj & 1) << 3) + lr;
    const int aseg = lj >> 1;
    const int brow = wn * 64 + ((lj >> 1) << 3) + lr;
    const int bseg = lj & 1;

    int buf = 0;
    for (int c = 0; c < 12; ++c) {
        CP_WAIT1();
        __syncthreads();
        if (c + 2 < 12) {
            int nb = buf + 2; if (nb >= 3) nb -= 3;
            sf_load(sb + nb * SF_STAGE, tid, Qb, Kb, qhb, qlb, khb, klb,
                    (c + 2) * 64);
        }
        CP_COMMIT();

        const uint32_t bb = sb + buf * SF_STAGE;
#pragma unroll
        for (int sub = 0; sub < 2; ++sub) {
            const uint32_t qoff = bb + sub * 8192;
            const uint32_t koff = bb + 16384 + sub * 8192;
#pragma unroll
            for (int ks = 0; ks < 2; ++ks) {
                uint32_t Af[2][4];
#pragma unroll
                for (int mt = 0; mt < 2; ++mt)
                    ldsm4(Af[mt], qoff + swz(arow + mt * 16, ks * 2 + aseg));
#pragma unroll
                for (int ntp = 0; ntp < 4; ++ntp) {
                    uint32_t Bf[4];
                    ldsm4(Bf, koff + swz(brow + ntp * 16, ks * 2 + bseg));
#pragma unroll
                    for (int mt = 0; mt < 2; ++mt)
#pragma unroll
                        for (int h = 0; h < 2; ++h)
                            mma16816(facc[mt][ntp * 2 + h], Af[mt], &Bf[h * 2]);
                }
            }
        }
#pragma unroll
        for (int step = 0; step < 2; ++step) {
            uint32_t A1f[2][4], A2f[2][4];
#pragma unroll
            for (int mt = 0; mt < 2; ++mt) {
                const uint32_t off = swz(arow + mt * 16, step * 2 + aseg);
                ldsm4(A1f[mt], bb + 32768 + off);
                ldsm4(A2f[mt], bb + 40960 + off);
            }
#pragma unroll
            for (int ntp = 0; ntp < 4; ++ntp) {
                const uint32_t off = swz(brow + ntp * 16, step * 2 + bseg);
                uint32_t B1f[4], B2f[4];
                ldsm4(B1f, bb + 49152 + off);
                ldsm4(B2f, bb + 57344 + off);
#pragma unroll
                for (int mt = 0; mt < 2; ++mt)
#pragma unroll
                    for (int h = 0; h < 2; ++h) {
                        int* cc = iacc[mt][ntp * 2 + h];
                        mma_s8(cc, A1f[mt], &B2f[h * 2]);
                        mma_s8(cc, A2f[mt], &B1f[h * 2]);
                    }
            }
        }
        ++buf; if (buf == 3) buf = 0;
    }

    const int rb = wm * 32 + (lane >> 2);
    const int cb = wn * 64 + (lane & 3) * 2;
    const long long zS = (long long)z * 4096 * 4096;
    const float inv2048 = 4.8828125e-4f;
#pragma unroll
    for (int mt = 0; mt < 2; ++mt)
#pragma unroll
        for (int rh = 0; rh < 2; ++rh) {
            const int lrw = rb + mt * 16 + rh * 8;
            const float sA = sq[(long long)z * 4096 + bm + lrw] * inv2048;
#pragma unroll
            for (int nt = 0; nt < 8; ++nt) {
                const int lc = cb + nt * 8;
                const float sB0 = sk[(long long)z * 4096 + bn + lc];
                const float sB1 = sk[(long long)z * 4096 + bn + lc + 1];
                float2 w;
                w.x = facc[mt][nt][rh * 2 + 0]
                    + sA * sB0 * (float)iacc[mt][nt][rh * 2 + 0];
                w.y = facc[mt][nt][rh * 2 + 1]
                    + sA * sB1 * (float)iacc[mt][nt][rh * 2 + 1];
                *(float2*)(S + zS + (bm + lrw) * 4096 + bn + lc) = w;
            }
        }
}

// ---------------- dual-acc double-level int8 GEMM (128x128) ----------
static constexpr int I8D_STAGE = 32768;
static constexpr int I8D_SMEM  = 3 * I8D_STAGE;

__device__ __forceinline__ void i8d_load(uint32_t so, int tid,
    const char* __restrict__ A1, const char* __restrict__ A2,
    const char* __restrict__ B1, const char* __restrict__ B2,
    long long k0, int K)
{
    const int r = tid & 127, hf = tid >> 7;
#pragma unroll
    for (int u = 0; u < 2; ++u) {
        const int s = hf * 2 + u;
        const uint32_t d = swz(r, s);
        const long long g = (long long)r * K + k0 + s * 16;
        cp16(so + d,         A1 + g);
        cp16(so + 8192 + d,  A2 + g);
        cp16(so + 16384 + d, B1 + g);
        cp16(so + 24576 + d, B2 + g);
    }
}

template <int MODE>
__global__ __launch_bounds__(256, 1)
void i8d_gemm(const char* __restrict__ A1, const char* __restrict__ A2,
              const char* __restrict__ B1, const char* __restrict__ B2,
              const float* __restrict__ sa1, const float* __restrict__ sb1,
              const float* __restrict__ bias,
              float* __restrict__ Cf, h16* __restrict__ Chi, h16* __restrict__ Clo,
              const int N, const int K,
              const long long bA, const long long bB, const long long bC,
              const int sAz, const int sBz)
{
    extern __shared__ __align__(128) char smem[];
    const uint32_t sbase = smem_u32(smem);
    const int tid = threadIdx.x;
    const int wid = tid >> 5, lane = tid & 31;
    const int wm = wid >> 1, wn = wid & 1;
    const int lj = lane >> 3, lr = lane & 7;
    const int z = blockIdx.z;
    const long long bm = (long long)blockIdx.y * 128;
    const long long bn = (long long)blockIdx.x * 128;

    const char* A1b = A1 + (long long)z * bA + bm * K;
    const char* A2b = A2 + (long long)z * bA + bm * K;
    const char* B1b = B1 + (long long)z * bB + bn * K;
    const char* B2b = B2 + (long long)z * bB + bn * K;
    const float* sa1v = sa1 + (long long)z * sAz + bm;
    const float* sb1v = sb1 + (long long)z * sBz + bn;

    int acc1[2][8][4], acc2[2][8][4];
#pragma unroll
    for (int i = 0; i < 2; ++i)
#pragma unroll
        for (int j = 0; j < 8; ++j)
#pragma unroll
            for (int t = 0; t < 4; ++t) { acc1[i][j][t] = 0; acc2[i][j][t] = 0; }

    const int NC = K / 64;
    i8d_load(sbase, tid, A1b, A2b, B1b, B2b, 0, K);
    CP_COMMIT();
    i8d_load(sbase + I8D_STAGE, tid, A1b, A2b, B1b, B2b, 64, K);
    CP_COMMIT();

    const int arow = wm * 32 + ((lj & 1) << 3) + lr;
    const int aso  = lj >> 1;
    const int brow = wn * 64 + ((lj >> 1) << 3) + lr;
    const int bso  = lj & 1;

    int buf = 0;
    for (int c = 0; c < NC; ++c) {
        CP_WAIT1();
        __syncthreads();
        if (c + 2 < NC) {
            int nb = buf + 2; if (nb >= 3) nb -= 3;
            i8d_load(sbase + nb * I8D_STAGE, tid, A1b, A2b, B1b, B2b,
                     (long long)(c + 2) * 64, K);
        }
        CP_COMMIT();

        const uint32_t bb = sbase + buf * I8D_STAGE;
#pragma unroll
        for (int step = 0; step < 2; ++step) {
            uint32_t A1f[2][4], A2f[2][4];
#pragma unroll
            for (int mt = 0; mt < 2; ++mt) {
                const uint32_t off = swz(arow + mt * 16, step * 2 + aso);
                ldsm4(A1f[mt], bb + off);
                ldsm4(A2f[mt], bb + 8192 + off);
            }
#pragma unroll
            for (int ntp = 0; ntp < 4; ++ntp) {
                const uint32_t off = swz(brow + ntp * 16, step * 2 + bso);
                uint32_t B1f[4], B2f[4];
                ldsm4(B1f, bb + 16384 + off);
                ldsm4(B2f, bb + 24576 + off);
#pragma unroll
                for (int mt = 0; mt < 2; ++mt)
#pragma unroll
                    for (int h = 0; h < 2; ++h) {
                        int* c1 = acc1[mt][ntp * 2 + h];
                        int* c2 = acc2[mt][ntp * 2 + h];
                        mma_s8(c1, A1f[mt], &B1f[h * 2]);
                        mma_s8(c2, A1f[mt], &B2f[h * 2]);
                        mma_s8(c2, A2f[mt], &B1f[h * 2]);
                    }
            }
        }
        ++buf; if (buf == 3) buf = 0;
    }

    const int rb = wm * 32 + (lane >> 2);
    const int cb = wn * 64 + (lane & 3) * 2;
    const long long zC = (long long)z * bC;
#pragma unroll
    for (int mt = 0; mt < 2; ++mt)
#pragma unroll
        for (int rh = 0; rh < 2; ++rh) {
            const int lrw = rb + mt * 16 + rh * 8;
            const float sA1 = sa1v[lrw];
#pragma unroll
            for (int nt = 0; nt < 8; ++nt) {
                const int lc = cb + nt * 8;
                const int x1a = acc1[mt][nt][rh * 2 + 0];
                const int x1b = acc1[mt][nt][rh * 2 + 1];
                const int x2a = acc2[mt][nt][rh * 2 + 0];
                const int x2b = acc2[mt][nt][rh * 2 + 1];
                float v0 = sA1 * sb1v[lc]
                         * ((float)x1a + (float)x2a * 0.00390625f);
                float v1 = sA1 * sb1v[lc + 1]
                         * ((float)x1b + (float)x2b * 0.00390625f);
                if (MODE >= 2) {
                    v0 += bias[(int)bn + lc];
                    v1 += bias[(int)bn + lc + 1];
                }
                if (MODE == 2) { v0 = fmaxf(v0, 0.f); v1 = fmaxf(v1, 0.f); }
                const long long o = zC + (bm + lrw) * N + bn + lc;
                if (MODE == 3) {
                    float2 w; w.x = v0; w.y = v1;
                    *(float2*)(Cf + o) = w;
                } else {
                    h16 h0, l0, h1, l1;
                    split2h(v0, h0, l0); split2h(v1, h1, l1);
                    *(__half2*)(Chi + o) = __halves2half2(h0, h1);
                    *(__half2*)(Clo + o) = __halves2half2(l0, l1);
                }
            }
        }
}

// -------- warp-per-row tied int8 quant, Q and K fused (L=768) --------
__global__ __launch_bounds__(256)
void quant_rows_v(const h16* __restrict__ Qh, const h16* __restrict__ Ql,
                  char* __restrict__ q8h_, char* __restrict__ q8l_,
                  float* __restrict__ sq_,
                  const h16* __restrict__ Kh, const h16* __restrict__ Kl,
                  char* __restrict__ k8h_, char* __restrict__ k8l_,
                  float* __restrict__ sk_)
{
    const int gw = blockIdx.x * 8 + (threadIdx.x >> 5);
    const int lane = threadIdx.x & 31;
    const h16 *ph, *pl;
    char *d1, *d2;
    float* sv;
    if (gw < 16384) {
        const long long r = gw;
        ph = Qh + r * 768; pl = Ql + r * 768;
        d1 = q8h_ + r * 768; d2 = q8l_ + r * 768; sv = sq_ + r;
    } else {
        const long long r = gw - 16384;
        ph = Kh + r * 768; pl = Kl + r * 768;
        d1 = k8h_ + r * 768; d2 = k8l_ + r * 768; sv = sk_ + r;
    }

    uint4 vh[3], vl[3];
#pragma unroll
    for (int u = 0; u < 3; ++u) {
        vh[u] = ((const uint4*)ph)[lane + u * 32];
        vl[u] = ((const uint4*)pl)[lane + u * 32];
    }
    float mh = 0.f;
#pragma unroll
    for (int u = 0; u < 3; ++u) {
        const h16* hp = (const h16*)&vh[u];
#pragma unroll
        for (int t = 0; t < 8; ++t)
            mh = fmaxf(mh, fabsf(__half2float(hp[t])));
    }
    mh = fmaxf(warp_max(mh), 1e-20f);
    const float ih = 127.f / mh;
    const float il = ih * 2048.f;

#pragma unroll
    for (int u = 0; u < 3; ++u) {
        const h16* hp = (const h16*)&vh[u];
        const h16* lp = (const h16*)&vl[u];
        int bh[8], bl[8];
#pragma unroll
        for (int t = 0; t < 8; ++t) {
            bh[t] = __float2int_rn(__half2float(hp[t]) * ih);
            bl[t] = clamp127(__float2int_rn(__half2float(lp[t]) * il));
        }
        uint2 wh, wl;
        wh.x = pack4(bh[0], bh[1], bh[2], bh[3]);
        wh.y = pack4(bh[4], bh[5], bh[6], bh[7]);
        wl.x = pack4(bl[0], bl[1], bl[2], bl[3]);
        wl.y = pack4(bl[4], bl[5], bl[6], bl[7]);
        ((uint2*)d1)[lane + u * 32] = wh;
        ((uint2*)d2)[lane + u * 32] = wl;
    }
    if (lane == 0) sv[0] = mh / 127.f;
}

// -------- warp-per-row double-level quant of fp16 pair (L % 256 == 0) --------
__global__ __launch_bounds__(256)
void quant_pd_v(const h16* __restrict__ Ah, const h16* __restrict__ Al,
                char* __restrict__ q1, char* __restrict__ q2,
                float* __restrict__ s, const int L)
{
    const long long row = blockIdx.x * 8 + (threadIdx.x >> 5);
    const int lane = threadIdx.x & 31;
    const uint4* ph = (const uint4*)(Ah + row * (long long)L);
    const uint4* pl = (const uint4*)(Al + row * (long long)L);
    const int nU = L >> 8;   // uint4 per lane

    float m = 0.f;
    for (int u = 0; u < nU; ++u) {
        const uint4 a = ph[lane + u * 32];
        const uint4 b = pl[lane + u * 32];
        const h16* hp = (const h16*)&a;
        const h16* lp = (const h16*)&b;
#pragma unroll
        for (int t = 0; t < 8; ++t)
            m = fmaxf(m, fabsf(__half2float(hp[t]) + __half2float(lp[t])));
    }
    m = fmaxf(warp_max(m), 1e-20f);
    const float inv = 127.f / m;

    uint2* o1 = (uint2*)(q1 + row * (long long)L);
    uint2* o2 = (uint2*)(q2 + row * (long long)L);
    for (int u = 0; u < nU; ++u) {
        const uint4 a = ph[lane + u * 32];
        const uint4 b = pl[lane + u * 32];
        const h16* hp = (const h16*)&a;
        const h16* lp = (const h16*)&b;
        int b1[8], b2[8];
#pragma unroll
        for (int t = 0; t < 8; ++t) {
            const float v = (__half2float(hp[t]) + __half2float(lp[t])) * inv;
            const int x = __float2int_rn(v);
            b1[t] = x;
            b2[t] = clamp127(__float2int_rn((v - (float)x) * 256.f));
        }
        uint2 w1, w2;
        w1.x = pack4(b1[0], b1[1], b1[2], b1[3]);
        w1.y = pack4(b1[4], b1[5], b1[6], b1[7]);
        w2.x = pack4(b2[0], b2[1], b2[2], b2[3]);
        w2.y = pack4(b2[4], b2[5], b2[6], b2[7]);
        o1[lane + u * 32] = w1;
        o2[lane + u * 32] = w2;
    }
    if (lane == 0) s[row] = m / 127.f;
}

// -------- warp-per-row double-level quant of fp32 (L % 128 == 0) --------
__global__ __launch_bounds__(256)
void quant_f32d_v(const float* __restrict__ A, char* __restrict__ q1,
                  char* __restrict__ q2, float* __restrict__ s, const int L)
{
    const long long row = blockIdx.x * 8 + (threadIdx.x >> 5);
    const int lane = threadIdx.x & 31;
    const float4* p = (const float4*)(A + row * (long long)L);
    const int nF = L >> 7;   // float4 per lane

    float m = 0.f;
    for (int u = 0; u < nF; ++u) {
        const float4 v = p[lane + u * 32];
        m = fmaxf(m, fmaxf(fmaxf(fabsf(v.x), fabsf(v.y)),
                           fmaxf(fabsf(v.z), fabsf(v.w))));
    }
    m = fmaxf(warp_max(m), 1e-20f);
    const float inv = 127.f / m;

    uint32_t* o1 = (uint32_t*)(q1 + row * (long long)L);
    uint32_t* o2 = (uint32_t*)(q2 + row * (long long)L);
    for (int u = 0; u < nF; ++u) {
        const float4 v = p[lane + u * 32];
        const float e[4] = {v.x * inv, v.y * inv, v.z * inv, v.w * inv};
        int b1[4], b2[4];
#pragma unroll
        for (int t = 0; t < 4; ++t) {
            const int x = __float2int_rn(e[t]);
            b1[t] = x;
            b2[t] = clamp127(__float2int_rn((e[t] - (float)x) * 256.f));
        }
        o1[lane + u * 32] = pack4(b1[0], b1[1], b1[2], b1[3]);
        o2[lane + u * 32] = pack4(b2[0], b2[1], b2[2], b2[3]);
    }
    if (lane == 0) s[row] = m / 127.f;
}

// ---------------- fp32 -> (hi,lo) fp16 (X) ----------------
__global__ __launch_bounds__(256)
void cvt_pair(const float* __restrict__ in, h16* __restrict__ hi,
              h16* __restrict__ lo, const long long n)
{
    const long long i = ((long long)blockIdx.x * 256 + threadIdx.x) * 4;
    if (i >= n) return;
    const float4 v = *(const float4*)(in + i);
    __align__(8) h16 h[4];
    __align__(8) h16 l[4];
    split2h(v.x, h[0], l[0]); split2h(v.y, h[1], l[1]);
    split2h(v.z, h[2], l[2]); split2h(v.w, h[3], l[3]);
    *(uint2*)(hi + i) = *(const uint2*)h;
    *(uint2*)(lo + i) = *(const uint2*)l;
}

// ---------------- 3 weights -> fused Wc pair in one launch ----------------
__global__ __launch_bounds__(256)
void cvt_pair3(const float* __restrict__ A, const float* __restrict__ B,
               const float* __restrict__ C, h16* __restrict__ hi,
               h16* __restrict__ lo)
{
    const int seg = blockIdx.x / 576;
    const long long base = (long long)seg * 768 * 768;
    const float* src = (seg == 0) ? A : (seg == 1) ? B : C;
    const long long i = ((long long)(blockIdx.x - seg * 576) * 256 + threadIdx.x) * 4;
    const float4 v = *(const float4*)(src + i);
    __align__(8) h16 h[4];
    __align__(8) h16 l[4];
    split2h(v.x, h[0], l[0]); split2h(v.y, h[1], l[1]);
    split2h(v.z, h[2], l[2]); split2h(v.w, h[3], l[3]);
    *(uint2*)(hi + base + i) = *(const uint2*)h;
    *(uint2*)(lo + base + i) = *(const uint2*)l;
}

// ---------------- V transpose: [b,4096,768]f32 -> [b,768,4096] fp32 ----------
__global__ __launch_bounds__(256)
void transpose_f32(const float* __restrict__ V, float* __restrict__ T)
{
    __shared__ float tile[32][33];
    const int b = blockIdx.z;
    const int e0 = blockIdx.x * 32;
    const int t0 = blockIdx.y * 32;
    const float* Vb = V + (long long)b * 4096 * 768;
    float* Tb = T + (long long)b * 768 * 4096;
    const int tx = threadIdx.x, ty = threadIdx.y;
#pragma unroll
    for (int j = 0; j < 32; j += 8)
        tile[ty + j][tx] = Vb[(long long)(t0 + ty + j) * 768 + e0 + tx];
    __syncthreads();
#pragma unroll
    for (int j = 0; j < 32; j += 8)
        Tb[(long long)(e0 + ty + j) * 4096 + t0 + tx] = tile[tx][ty + j];
}

// ---------------- softmax (rows of 4096) -> double-level int8 ----------------
__global__ __launch_bounds__(256)
void softmax_i8(const float* __restrict__ S, char* __restrict__ p8a,
                char* __restrict__ p8b, float* __restrict__ sp)
{
    __shared__ float red[8];
    const long long row = blockIdx.x;
    const float* p = S + row * 4096;
    const int tid = threadIdx.x, lane = tid & 31, warp = tid >> 5;

    float4 v[4];
#pragma unroll
    for (int i = 0; i < 4; ++i)
        v[i] = *(const float4*)(p + tid * 4 + i * 1024);

    float mx = -3.402823466e38f;
#pragma unroll
    for (int i = 0; i < 4; ++i)
        mx = fmaxf(mx, fmaxf(fmaxf(v[i].x, v[i].y), fmaxf(v[i].z, v[i].w)));
    mx = warp_max(mx);
    if (lane == 0) red[warp] = mx;
    __syncthreads();
    float rowmax = red[0];
#pragma unroll
    for (int w = 1; w < 8; ++w) rowmax = fmaxf(rowmax, red[w]);
    __syncthreads();

    float sum = 0.0f;
#pragma unroll
    for (int i = 0; i < 4; ++i) {
        v[i].x = __expf(v[i].x - rowmax);
        v[i].y = __expf(v[i].y - rowmax);
        v[i].z = __expf(v[i].z - rowmax);
        v[i].w = __expf(v[i].w - rowmax);
        sum += (v[i].x + v[i].y) + (v[i].z + v[i].w);
    }
#pragma unroll
    for (int o = 16; o > 0; o >>= 1)
        sum += __shfl_xor_sync(0xffffffffu, sum, o);
    if (lane == 0) red[warp] = sum;
    __syncthreads();
    float rowsum = 0.0f;
#pragma unroll
    for (int w = 0; w < 8; ++w) rowsum += red[w];

#pragma unroll
    for (int i = 0; i < 4; ++i) {
        int q1[4], q2[4];
        const float e[4] = {v[i].x, v[i].y, v[i].z, v[i].w};
#pragma unroll
        for (int t = 0; t < 4; ++t) {
            const float u = 127.f * e[t];
            q1[t] = __float2int_rn(u);
            q2[t] = clamp127(__float2int_rn((u - (float)q1[t]) * 256.f));
        }
        const long long o = row * 4096 + tid * 4 + i * 1024;
        *(uint32_t*)(p8a + o) = pack4(q1[0], q1[1], q1[2], q1[3]);
        *(uint32_t*)(p8b + o) = pack4(q2[0], q2[1], q2[2], q2[3]);
    }
    if (tid == 0) sp[row] = (1.0f / rowsum) / 127.f;
}

// ---------------- host ----------------
extern "C" void kernel_launch(void* const* d_in, const int* in_sizes, int n_in,
                              void* d_out, int out_size)
{
    const float* X  = (const float*)d_in[0];
    const float* Wq = (const float*)d_in[1];
    const float* Wk = (const float*)d_in[2];
    const float* Wv = (const float*)d_in[3];
    const float* W1 = (const float*)d_in[4];
    const float* b1 = (const float*)d_in[5];
    const float* W2 = (const float*)d_in[6];
    const float* b2 = (const float*)d_in[7];
    float* out = (float*)d_out;

    h16 *Xh, *Xl, *Wch, *Wcl, *Qh, *Ql, *Kh, *Kl, *NVh, *NVl, *Hh, *Hl;
    float *Vf, *VTf, *S;
    char *q8h, *q8l, *k8h, *k8l;
    float *sqh, *skh;
    char *p8a, *p8b, *vt8a, *vt8b, *nv8a, *nv8b, *h8a, *h8b;
    char *w18a, *w18b, *w28a, *w28b;
    float *sp, *svt, *snv, *sH, *sw1, *sw2;
    cudaGetSymbolAddress((void**)&Xh, g_Xh);     cudaGetSymbolAddress((void**)&Xl, g_Xl);
    cudaGetSymbolAddress((void**)&Wch, g_Wch);   cudaGetSymbolAddress((void**)&Wcl, g_Wcl);
    cudaGetSymbolAddress((void**)&Qh, g_Qh);     cudaGetSymbolAddress((void**)&Ql, g_Ql);
    cudaGetSymbolAddress((void**)&Kh, g_Kh);     cudaGetSymbolAddress((void**)&Kl, g_Kl);
    cudaGetSymbolAddress((void**)&Vf, g_Vf);     cudaGetSymbolAddress((void**)&VTf, g_VTf);
    cudaGetSymbolAddress((void**)&S, g_S);
    cudaGetSymbolAddress((void**)&NVh, g_NVh);   cudaGetSymbolAddress((void**)&NVl, g_NVl);
    cudaGetSymbolAddress((void**)&Hh, g_Hh);     cudaGetSymbolAddress((void**)&Hl, g_Hl);
    cudaGetSymbolAddress((void**)&q8h, g_q8h);   cudaGetSymbolAddress((void**)&q8l, g_q8l);
    cudaGetSymbolAddress((void**)&k8h, g_k8h);   cudaGetSymbolAddress((void**)&k8l, g_k8l);
    cudaGetSymbolAddress((void**)&sqh, g_sqh);   cudaGetSymbolAddress((void**)&skh, g_skh);
    cudaGetSymbolAddress((void**)&p8a, g_p8a);   cudaGetSymbolAddress((void**)&p8b, g_p8b);
    cudaGetSymbolAddress((void**)&vt8a, g_vt8a); cudaGetSymbolAddress((void**)&vt8b, g_vt8b);
    cudaGetSymbolAddress((void**)&nv8a, g_nv8a); cudaGetSymbolAddress((void**)&nv8b, g_nv8b);
    cudaGetSymbolAddress((void**)&h8a, g_h8a);   cudaGetSymbolAddress((void**)&h8b, g_h8b);
    cudaGetSymbolAddress((void**)&w18a, g_w18a); cudaGetSymbolAddress((void**)&w18b, g_w18b);
    cudaGetSymbolAddress((void**)&w28a, g_w28a); cudaGetSymbolAddress((void**)&w28b, g_w28b);
    cudaGetSymbolAddress((void**)&sp, g_sp);     cudaGetSymbolAddress((void**)&svt, g_svt);
    cudaGetSymbolAddress((void**)&snv, g_snv);   cudaGetSymbolAddress((void**)&sH, g_sH);
    cudaGetSymbolAddress((void**)&sw1, g_sw1);   cudaGetSymbolAddress((void**)&sw2, g_sw2);

    cudaFuncSetAttribute(wm_gemm_qkv,
                         cudaFuncAttributeMaxDynamicSharedMemorySize, SMEM_TOTAL);
    cudaFuncSetAttribute(scores_fused,
                         cudaFuncAttributeMaxDynamicSharedMemorySize, SF_SMEM);
    cudaFuncSetAttribute(i8d_gemm<1>,
                         cudaFuncAttributeMaxDynamicSharedMemorySize, I8D_SMEM);
    cudaFuncSetAttribute(i8d_gemm<2>,
                         cudaFuncAttributeMaxDynamicSharedMemorySize, I8D_SMEM);
    cudaFuncSetAttribute(i8d_gemm<3>,
                         cudaFuncAttributeMaxDynamicSharedMemorySize, I8D_SMEM);

    // 0-3: input conversions
    cvt_pair<<<12288, 256>>>(X, Xh, Xl, 16384LL * 768);
    cvt_pair3<<<1728, 256>>>(Wq, Wk, Wv, Wch, Wcl);
    quant_f32d_v<<<384, 256>>>(W1, w18a, w18b, sw1, 768);
    quant_f32d_v<<<96,  256>>>(W2, w28a, w28b, sw2, 3072);

    // 4: fused QKV
    wm_gemm_qkv<<<dim3(18, 128, 1), 256, SMEM_TOTAL>>>(
        Xh, Xl, Wch, Wcl, Vf, Qh, Ql, Kh, Kl, 2304, 768);

    // 5: Q + K tied int8 quant (ncu window target)
    quant_rows_v<<<4096, 256>>>(Qh, Ql, q8h, q8l, sqh, Kh, Kl, k8h, k8l, skh);

    // 6-7: V transpose + quant
    transpose_f32<<<dim3(24, 128, 4), dim3(32, 8)>>>(Vf, VTf);
    quant_f32d_v<<<384, 256>>>(VTf, vt8a, vt8b, svt, 4096);

    // 8: fused scores
    scores_fused<<<dim3(32, 32, 4), 256, SF_SMEM>>>(
        Qh, Kh, q8h, q8l, k8h, k8l, sqh, skh, S);

    // 9: softmax -> double-level int8 P
    softmax_i8<<<16384, 256>>>(S, p8a, p8b, sp);

    // 10: attn@V
    i8d_gemm<1><<<dim3(6, 32, 4), 256, I8D_SMEM>>>(
        p8a, p8b, vt8a, vt8b, sp, svt, nullptr,
        nullptr, NVh, NVl, 768, 4096,
        4096LL * 4096, 768LL * 4096, 4096LL * 768, 4096, 768);

    // 11-12: FFN1
    quant_pd_v<<<2048, 256>>>(NVh, NVl, nv8a, nv8b, snv, 768);
    i8d_gemm<2><<<dim3(24, 128, 1), 256, I8D_SMEM>>>(
        nv8a, nv8b, w18a, w18b, snv, sw1, b1,
        nullptr, Hh, Hl, 3072, 768, 0, 0, 0, 0, 0);

    // 13-14: FFN2
    quant_pd_v<<<2048, 256>>>(Hh, Hl, h8a, h8b, sH, 3072);
    i8d_gemm<3><<<dim3(6, 128, 1), 256, I8D_SMEM>>>(
        h8a, h8b, w28a, w28b, sH, sw2, b2,
        out, nullptr, nullptr, 768, 3072, 0, 0, 0, 0, 0);
}